// round 6
// baseline (speedup 1.0000x reference)
#include <cuda_runtime.h>
#include <cuda_bf16.h>
#include <cub/cub.cuh>
#include <math.h>
#include <stdint.h>

// ---------------- constants ----------------
#define Hh 64
#define Ww 64
#define Cc 512
#define Mm 512
#define Nn 4
#define Aa 9
#define NPIX (Hh*Ww)              // 4096
#define NANCH (NPIX*Aa)           // 36864
#define PRE_N 3000
#define POST_N 300

#define LOC_OFF   0u
#define SCORE_OFF 589824u
#define ROIS_OFF  884736u
#define RI_OFF    889536u
#define ANCH_OFF  890736u

#define XSZ ((size_t)Nn*NPIX*Cc)   // elements per split term of x (NHWC)

// ---------------- static device scratch ----------------
__device__ float g_feat[(size_t)Nn*NPIX*Cc];            // NHWC feat fp32, 33.5MB
__device__ __nv_bfloat16 g_xt[3*XSZ];                   // 3 bf16 split terms of x, NHWC
__device__ __nv_bfloat16 g_ws[(size_t)3*9*512*512];     // 3 terms of W, [term][k][m][c]
__device__ float g_keys_in[Nn*NANCH];
__device__ float g_keys_out[Nn*NANCH];
__device__ int   g_vals_in[Nn*NANCH];
__device__ int   g_vals_out[Nn*NANCH];
__device__ int   g_offs[5];
__device__ float g_boxes[(size_t)Nn*NANCH*4];
__device__ float g_top[Nn*PRE_N*4];
__device__ float g_area[Nn*PRE_N];
__device__ unsigned long long g_cub_temp[(32u<<20)/8];  // 32MB

struct AB9 { float v[36]; };

// ================= helpers (baseline ISA only: sm_80-era) =================
__device__ __forceinline__ uint32_t smem_u32(const void* p) {
    uint32_t a;
    asm("{ .reg .u64 t; cvta.to.shared.u64 t, %1; cvt.u32.u64 %0, t; }" : "=r"(a) : "l"(p));
    return a;
}
__device__ __forceinline__ void cp16(uint32_t dst, const void* src, int sz) {
    asm volatile("cp.async.ca.shared.global [%0], [%1], 16, %2;"
                 :: "r"(dst), "l"(__cvta_generic_to_global(src)), "r"(sz));
}
__device__ __forceinline__ void cp_commit() {
    asm volatile("cp.async.commit_group;" ::: "memory");
}
__device__ __forceinline__ void cp_wait1() {
    asm volatile("cp.async.wait_group 1;" ::: "memory");
}
__device__ __forceinline__ void cp_wait0() {
    asm volatile("cp.async.wait_group 0;" ::: "memory");
}
__device__ __forceinline__ void ldsm4(uint32_t* r, uint32_t addr) {
    asm volatile("ldmatrix.sync.aligned.m8n8.x4.shared.b16 {%0,%1,%2,%3}, [%4];"
                 : "=r"(r[0]), "=r"(r[1]), "=r"(r[2]), "=r"(r[3]) : "r"(addr));
}
__device__ __forceinline__ void mma16816(float* d, const uint32_t* a, uint32_t b0, uint32_t b1) {
    asm volatile(
        "mma.sync.aligned.m16n8k16.row.col.f32.bf16.bf16.f32 "
        "{%0,%1,%2,%3}, {%4,%5,%6,%7}, {%8,%9}, {%0,%1,%2,%3};"
        : "+f"(d[0]), "+f"(d[1]), "+f"(d[2]), "+f"(d[3])
        : "r"(a[0]), "r"(a[1]), "r"(a[2]), "r"(a[3]), "r"(b0), "r"(b1));
}

// ================= setup: split x into 3 bf16 terms, NCHW -> NHWC =================
__global__ void split_x_kernel(const float* __restrict__ x) {
    __shared__ float t[32][33];
    int n = blockIdx.z, c0 = blockIdx.x * 32, p0 = blockIdx.y * 32;
    int tx = threadIdx.x & 31, ty = threadIdx.x >> 5;
    const float* xn = x + (size_t)n * Cc * NPIX;
#pragma unroll
    for (int kk = 0; kk < 4; kk++) {
        int c = c0 + ty + kk * 8;
        t[ty + kk * 8][tx] = xn[(size_t)c * NPIX + p0 + tx];
    }
    __syncthreads();
#pragma unroll
    for (int kk = 0; kk < 4; kk++) {
        int p = p0 + ty + kk * 8;
        int c = c0 + tx;
        float v = t[tx][ty + kk * 8];
        __nv_bfloat16 a1 = __float2bfloat16(v);
        float r1 = v - __bfloat162float(a1);
        __nv_bfloat16 a2 = __float2bfloat16(r1);
        float r2 = r1 - __bfloat162float(a2);
        __nv_bfloat16 a3 = __float2bfloat16(r2);
        size_t idx = ((size_t)n * NPIX + p) * Cc + c;
        g_xt[idx] = a1;
        g_xt[XSZ + idx] = a2;
        g_xt[2 * XSZ + idx] = a3;
    }
}

// ================= setup: split W into 3 bf16 terms, OIHW -> [term][k][m][c] ========
__global__ void split_w_kernel(const float* __restrict__ w) {
    int idx = blockIdx.x * 256 + threadIdx.x;
    if (idx >= Mm * Cc) return;
    int m = idx >> 9, c = idx & 511;
#pragma unroll
    for (int k = 0; k < 9; k++) {
        float v = w[(size_t)m * (Cc * 9) + c * 9 + k];
        __nv_bfloat16 a1 = __float2bfloat16(v);
        float r1 = v - __bfloat162float(a1);
        __nv_bfloat16 a2 = __float2bfloat16(r1);
        float r2 = r1 - __bfloat162float(a2);
        __nv_bfloat16 a3 = __float2bfloat16(r2);
        size_t o = ((size_t)k * 512 + m) * 512 + c;
        g_ws[o] = a1;
        g_ws[(size_t)9 * 512 * 512 + o] = a2;
        g_ws[(size_t)2 * 9 * 512 * 512 + o] = a3;
    }
}

// ================= HMMA implicit-GEMM conv (bf16x3 split, fp32 accum) =================
// grid (128 px-blocks of 128, 4 oc-blocks of 128), 256 threads (8 warps: 2m x 4n)
// 576 stages = 9 taps x 8 chunks(64ch) x 8 combos; A loaded at combos 0,3,6
// Dual accumulators: acc0 (a0*w0) + accS (all small combos), merged in epilogue.
#define NST 576
__device__ __constant__ int c_at[8] = {0, 0, 0, 1, 1, 1, 2, 2};
__device__ __constant__ int c_wt[8] = {0, 1, 2, 0, 1, 2, 0, 1};
__device__ __constant__ int c_al[8] = {1, 0, 0, 1, 0, 0, 1, 0};

__global__ __launch_bounds__(256, 1) void conv_hmma_kernel(const float* __restrict__ bias) {
    extern __shared__ char dsm_raw[];
    char* smem = dsm_raw + ((128 - ((uintptr_t)dsm_raw & 127)) & 127);
    // layout: A buffers [0,16K),[16K,32K); B buffers [32K,48K),[48K,64K)
    uint32_t base = smem_u32(smem);

    int tid = threadIdx.x;
    int wid = tid >> 5, lane = tid & 31;
    int wm = wid >> 2, wn = wid & 3;          // warp tile: m 64, n 32
    int pxb = blockIdx.x;                     // 128 px per block
    int oc0 = blockIdx.y * 128;

    float acc0[4][4][4];
    float accS[4][4][4];
#pragma unroll
    for (int i = 0; i < 4; i++)
#pragma unroll
        for (int j = 0; j < 4; j++)
#pragma unroll
            for (int k = 0; k < 4; k++) { acc0[i][j][k] = 0.f; accS[i][j][k] = 0.f; }

    int cur_ab = 1;        // toggles to 0 on first A load
    int ab_pipe[2];

    for (int s = 0; s <= NST; s++) {
        // ---- issue loads for stage s ----
        if (s < NST) {
            int tap = s >> 6;                  // 0..8
            int rem = s & 63;
            int chunk = rem >> 3;              // 0..7
            int combo = rem & 7;               // 0..7
            int dy = tap / 3 - 1, dx = tap % 3 - 1;
            if (c_al[combo]) {
                cur_ab ^= 1;
                const __nv_bfloat16* xa = g_xt + (size_t)c_at[combo] * XSZ;
                uint32_t abase = base + cur_ab * 16384u;
#pragma unroll
                for (int i = 0; i < 4; i++) {
                    int v = tid + i * 256;         // 0..1023
                    int r = v >> 3, c16 = v & 7;
                    int P = pxb * 128 + r;
                    int n = P >> 12, y = (P >> 6) & 63, x = P & 63;
                    int yy = y + dy, xx = x + dx;
                    bool ok = ((unsigned)yy < 64u) & ((unsigned)xx < 64u);
                    int pix = (n << 12) + (ok ? ((yy << 6) + xx) : 0);
                    const void* src = xa + ((size_t)pix << 9) + chunk * 64 + c16 * 8;
                    uint32_t off = (uint32_t)(r * 128) + (uint32_t)((c16 * 16) ^ ((r & 7) << 4));
                    cp16(abase + off, src, ok ? 16 : 0);
                }
            }
            ab_pipe[s & 1] = cur_ab;
            {
                const __nv_bfloat16* wb =
                    g_ws + (((size_t)c_wt[combo] * 9 + tap) * 512 + oc0) * 512;
                uint32_t bbase = base + 32768u + (s & 1) * 16384u;
#pragma unroll
                for (int i = 0; i < 4; i++) {
                    int v = tid + i * 256;
                    int r = v >> 3, c16 = v & 7;
                    const void* src = wb + (size_t)r * 512 + chunk * 64 + c16 * 8;
                    uint32_t off = (uint32_t)(r * 128) + (uint32_t)((c16 * 16) ^ ((r & 7) << 4));
                    cp16(bbase + off, src, 16);
                }
            }
            cp_commit();
        }
        // ---- compute stage s-1 ----
        if (s > 0) {
            if (s == NST) cp_wait0(); else cp_wait1();
            __syncthreads();
            int pcombo = (s - 1) & 7;
            uint32_t aB = base + (uint32_t)ab_pipe[(s - 1) & 1] * 16384u;
            uint32_t bB = base + 32768u + ((s - 1) & 1) * 16384u;
            int cg = lane >> 4;
            int arow0 = wm * 64 + (lane & 15);
            int brow0 = wn * 32 + (lane & 15);
#pragma unroll
            for (int ks = 0; ks < 4; ks++) {
                uint32_t coff = (uint32_t)((ks * 2 + cg) * 16);
                uint32_t a[4][4];
#pragma unroll
                for (int mt = 0; mt < 4; mt++) {
                    int row = arow0 + mt * 16;
                    uint32_t off = (uint32_t)(row * 128) + (coff ^ (uint32_t)((row & 7) << 4));
                    ldsm4(a[mt], aB + off);
                }
                uint32_t b[2][4];
#pragma unroll
                for (int bt = 0; bt < 2; bt++) {
                    int row = brow0 + bt * 16;
                    uint32_t off = (uint32_t)(row * 128) + (coff ^ (uint32_t)((row & 7) << 4));
                    ldsm4(b[bt], bB + off);
                }
                if (pcombo == 0) {
#pragma unroll
                    for (int mt = 0; mt < 4; mt++) {
                        mma16816(acc0[mt][0], a[mt], b[0][0], b[0][2]);
                        mma16816(acc0[mt][1], a[mt], b[0][1], b[0][3]);
                        mma16816(acc0[mt][2], a[mt], b[1][0], b[1][2]);
                        mma16816(acc0[mt][3], a[mt], b[1][1], b[1][3]);
                    }
                } else {
#pragma unroll
                    for (int mt = 0; mt < 4; mt++) {
                        mma16816(accS[mt][0], a[mt], b[0][0], b[0][2]);
                        mma16816(accS[mt][1], a[mt], b[0][1], b[0][3]);
                        mma16816(accS[mt][2], a[mt], b[1][0], b[1][2]);
                        mma16816(accS[mt][3], a[mt], b[1][1], b[1][3]);
                    }
                }
            }
            __syncthreads();
        }
    }

    // ---- epilogue: merge accumulators, bias + relu -> g_feat (NHWC fp32) ----
#pragma unroll
    for (int mt = 0; mt < 4; mt++) {
        int px0 = pxb * 128 + wm * 64 + mt * 16 + (lane >> 2);
#pragma unroll
        for (int nt = 0; nt < 4; nt++) {
            int oc = oc0 + wn * 32 + nt * 8 + (lane & 3) * 2;
            float2 bv = *(const float2*)&bias[oc];
            float2 o0, o1;
            o0.x = fmaxf((acc0[mt][nt][0] + accS[mt][nt][0]) + bv.x, 0.f);
            o0.y = fmaxf((acc0[mt][nt][1] + accS[mt][nt][1]) + bv.y, 0.f);
            o1.x = fmaxf((acc0[mt][nt][2] + accS[mt][nt][2]) + bv.x, 0.f);
            o1.y = fmaxf((acc0[mt][nt][3] + accS[mt][nt][3]) + bv.y, 0.f);
            *(float2*)&g_feat[(size_t)px0 * 512 + oc] = o0;
            *(float2*)&g_feat[(size_t)(px0 + 8) * 512 + oc] = o1;
        }
    }
}

// ---------------- 1x1 head + softmax + decode + clip + mask ----------------
__device__ __forceinline__ float readdim(const void* p) {
    int v = *(const int*)p;
    if (v > 0 && v < 1048576) return (float)v;
    return *(const float*)p;
}

// grid (512, 4), 256 threads = 8 warps; warp handles one pixel
__global__ __launch_bounds__(256) void rpn_head_kernel(
    const float* __restrict__ w_score, const float* __restrict__ b_score,
    const float* __restrict__ w_loc,   const float* __restrict__ b_loc,
    AB9 ab, const void* ihp, const void* iwp, float* __restrict__ out) {
    __shared__ float sh[8][56];
    int wid = threadIdx.x >> 5, lane = threadIdx.x & 31;
    int p = blockIdx.x * 8 + wid;
    int n = blockIdx.y;

    const float* f = g_feat + ((size_t)n * NPIX + p) * Cc;
    float fv[16];
#pragma unroll
    for (int i = 0; i < 16; i++) fv[i] = f[lane + 32 * i];

#pragma unroll 1
    for (int o = 0; o < 18; o++) {
        const float* w = w_score + o * Cc;
        float a = 0.f;
#pragma unroll
        for (int i = 0; i < 16; i++) a = fmaf(fv[i], w[lane + 32 * i], a);
#pragma unroll
        for (int s = 16; s; s >>= 1) a += __shfl_xor_sync(0xffffffffu, a, s);
        if (lane == 0) sh[wid][o] = a + b_score[o];
    }
#pragma unroll 1
    for (int o = 0; o < 36; o++) {
        const float* w = w_loc + o * Cc;
        float a = 0.f;
#pragma unroll
        for (int i = 0; i < 16; i++) a = fmaf(fv[i], w[lane + 32 * i], a);
#pragma unroll
        for (int s = 16; s; s >>= 1) a += __shfl_xor_sync(0xffffffffu, a, s);
        if (lane == 0) sh[wid][18 + o] = a + b_loc[o];
    }
    __syncwarp();

    if (lane < 9) {
        int a = lane;
        float s0 = sh[wid][a * 2], s1 = sh[wid][a * 2 + 1];
        size_t pa = (size_t)n * NANCH + (size_t)p * 9 + a;
        out[SCORE_OFF + pa * 2 + 0] = s0;
        out[SCORE_OFF + pa * 2 + 1] = s1;
        float l0 = sh[wid][18 + a * 4 + 0];
        float l1 = sh[wid][18 + a * 4 + 1];
        float l2 = sh[wid][18 + a * 4 + 2];
        float l3 = sh[wid][18 + a * 4 + 3];
        out[LOC_OFF + pa * 4 + 0] = l0;
        out[LOC_OFF + pa * 4 + 1] = l1;
        out[LOC_OFF + pa * 4 + 2] = l2;
        out[LOC_OFF + pa * 4 + 3] = l3;

        int py = p >> 6, px = p & 63;
        float sx = px * 16.f, sy = py * 16.f;
        float a0 = sx + ab.v[a * 4 + 0];
        float a1 = sy + ab.v[a * 4 + 1];
        float a2 = sx + ab.v[a * 4 + 2];
        float a3 = sy + ab.v[a * 4 + 3];
        if (n == 0) {
            size_t q = ((size_t)p * 9 + a) * 4;
            out[ANCH_OFF + q + 0] = a0;
            out[ANCH_OFF + q + 1] = a1;
            out[ANCH_OFF + q + 2] = a2;
            out[ANCH_OFF + q + 3] = a3;
        }
        float aw = a2 - a0, ah = a3 - a1;
        float cx = a0 + 0.5f * aw, cy = a1 + 0.5f * ah;
        float ncx = l0 * aw + cx, ncy = l1 * ah + cy;
        float nw = expf(l2) * aw, nh = expf(l3) * ah;
        float r0 = ncx - 0.5f * nw, r1 = ncy - 0.5f * nh;
        float r2 = ncx + 0.5f * nw, r3 = ncy + 0.5f * nh;
        float Wd = readdim(iwp), Hd = readdim(ihp);
        r0 = fminf(fmaxf(r0, 0.f), Wd);
        r1 = fminf(fmaxf(r1, 0.f), Hd);
        r2 = fminf(fmaxf(r2, 0.f), Wd);
        r3 = fminf(fmaxf(r3, 0.f), Hd);
        bool valid = ((r2 - r0) >= 16.f) && ((r3 - r1) >= 16.f);
        float m = fmaxf(s0, s1);
        float e0 = expf(s0 - m), e1 = expf(s1 - m);
        float fg = __fdiv_rn(e1, e0 + e1);
        g_keys_in[pa] = valid ? fg : -1e9f;
        float4 b4; b4.x = r0; b4.y = r1; b4.z = r2; b4.w = r3;
        ((float4*)g_boxes)[pa] = b4;
    }
}

// ---------------- sort setup ----------------
__global__ void init_sort_kernel() {
    int idx = blockIdx.x * 256 + threadIdx.x;
    if (idx < Nn * NANCH) g_vals_in[idx] = idx % NANCH;
    if (idx < 5) g_offs[idx] = idx * NANCH;
}

// ---------------- gather top-3000 boxes ----------------
__global__ void gather_kernel() {
    int idx = blockIdx.x * 256 + threadIdx.x;
    if (idx >= Nn * PRE_N) return;
    int n = idx / PRE_N, i = idx % PRE_N;
    int v = g_vals_out[n * NANCH + i];
    float4 b = ((const float4*)g_boxes)[(size_t)n * NANCH + v];
    ((float4*)g_top)[idx] = b;
    g_area[idx] = (b.z - b.x) * (b.w - b.y);
}

// ---------------- greedy NMS, one block per image ----------------
__global__ __launch_bounds__(256) void nms_kernel(float* __restrict__ out) {
    int n = blockIdx.x;
    int tid = threadIdx.x;
    __shared__ unsigned char sup[PRE_N];
    __shared__ int sel[POST_N];
    for (int i = tid; i < PRE_N; i += 256) sup[i] = 0;
    __syncthreads();

    const float* B = g_top + n * PRE_N * 4;
    const float* A = g_area + n * PRE_N;
    int cnt = 0;
    for (int i = 0; i < PRE_N; i++) {
        if (sup[i]) continue;
        if (tid == 0) sel[cnt] = i;
        cnt++;
        if (cnt == POST_N) break;
        float x1 = B[i * 4 + 0], y1 = B[i * 4 + 1];
        float x2 = B[i * 4 + 2], y2 = B[i * 4 + 3];
        float ai = A[i];
        for (int j = i + 1 + tid; j < PRE_N; j += 256) {
            if (!sup[j]) {
                float xx1 = fmaxf(x1, B[j * 4 + 0]);
                float yy1 = fmaxf(y1, B[j * 4 + 1]);
                float xx2 = fminf(x2, B[j * 4 + 2]);
                float yy2 = fminf(y2, B[j * 4 + 3]);
                float inter = fmaxf(xx2 - xx1, 0.f) * fmaxf(yy2 - yy1, 0.f);
                float iou = __fdiv_rn(inter, ai + A[j] - inter + 1e-9f);
                if (iou > 0.7f) sup[j] = 1;
            }
        }
        __syncthreads();
    }
    __syncthreads();
    for (int k = tid; k < POST_N; k += 256) {
        int s = (k < cnt) ? sel[k] : 0;
        float4 b = ((const float4*)g_top)[n * PRE_N + s];
        size_t q = ((size_t)n * POST_N + k) * 4;
        out[ROIS_OFF + q + 0] = b.x;
        out[ROIS_OFF + q + 1] = b.y;
        out[ROIS_OFF + q + 2] = b.z;
        out[ROIS_OFF + q + 3] = b.w;
        out[RI_OFF + (size_t)n * POST_N + k] = (float)n;
    }
}

// ---------------- host: anchor base exactly like numpy (f64 -> f32) ----------------
static AB9 make_ab() {
    double ratios[3] = {0.5, 1.0, 2.0};
    double scales[3] = {8.0, 16.0, 32.0};
    AB9 r;
    for (int i = 0; i < 3; i++)
        for (int j = 0; j < 3; j++) {
            double h = 16.0 * scales[j] * sqrt(ratios[i]);
            double w = 16.0 * scales[j] * sqrt(1.0 / ratios[i]);
            int a = i * 3 + j;
            r.v[a * 4 + 0] = (float)(8.0 - w / 2.0);
            r.v[a * 4 + 1] = (float)(8.0 - h / 2.0);
            r.v[a * 4 + 2] = (float)(8.0 + w / 2.0);
            r.v[a * 4 + 3] = (float)(8.0 + h / 2.0);
        }
    return r;
}

extern "C" void kernel_launch(void* const* d_in, const int* in_sizes, int n_in,
                              void* d_out, int out_size) {
    const float* x       = (const float*)d_in[0];
    const float* w_conv  = (const float*)d_in[1];
    const float* b_conv  = (const float*)d_in[2];
    const float* w_score = (const float*)d_in[3];
    const float* b_score = (const float*)d_in[4];
    const float* w_loc   = (const float*)d_in[5];
    const float* b_loc   = (const float*)d_in[6];
    const void*  ihp     = d_in[7];
    const void*  iwp     = d_in[8];
    float* out = (float*)d_out;

    AB9 ab = make_ab();

    static int smem_set = 0;
    if (!smem_set) {
        cudaFuncSetAttribute(conv_hmma_kernel,
                             cudaFuncAttributeMaxDynamicSharedMemorySize, 66048);
        smem_set = 1;
    }

    // 1) split x -> 3 bf16 NHWC terms; split W -> 3 bf16 [k][m][c] terms
    split_x_kernel<<<dim3(Cc / 32, NPIX / 32, Nn), 256>>>(x);
    split_w_kernel<<<(Mm * Cc + 255) / 256, 256>>>(w_conv);

    // 2) HMMA implicit-GEMM 3x3 conv (bf16x3 split, 8 combos, dual-acc) + bias + relu
    conv_hmma_kernel<<<dim3(Nn * NPIX / 128, 4), 256, 66048>>>(b_conv);

    // 3) 1x1 heads + softmax + decode + clip + mask
    rpn_head_kernel<<<dim3(NPIX / 8, Nn), 256>>>(w_score, b_score, w_loc, b_loc,
                                                 ab, ihp, iwp, out);

    // 4) sort setup
    init_sort_kernel<<<(Nn * NANCH + 255) / 256, 256>>>();

    // 5) stable descending segmented sort (matches jax.lax.top_k tie semantics)
    void *keys_in, *keys_out, *vals_in, *vals_out, *offs, *tmp;
    cudaGetSymbolAddress(&keys_in, g_keys_in);
    cudaGetSymbolAddress(&keys_out, g_keys_out);
    cudaGetSymbolAddress(&vals_in, g_vals_in);
    cudaGetSymbolAddress(&vals_out, g_vals_out);
    cudaGetSymbolAddress(&offs, g_offs);
    cudaGetSymbolAddress(&tmp, g_cub_temp);
    size_t temp_bytes = sizeof(g_cub_temp);
    cub::DeviceSegmentedRadixSort::SortPairsDescending(
        tmp, temp_bytes,
        (const float*)keys_in, (float*)keys_out,
        (const int*)vals_in, (int*)vals_out,
        Nn * NANCH, Nn, (const int*)offs, (const int*)offs + 1,
        0, 32, (cudaStream_t)0);

    // 6) gather top-3000 boxes + areas
    gather_kernel<<<(Nn * PRE_N + 255) / 256, 256>>>();

    // 7) greedy NMS -> rois + roi_indices
    nms_kernel<<<Nn, 256>>>(out);
}

// round 7
// speedup vs baseline: 1.6071x; 1.6071x over previous
#include <cuda_runtime.h>
#include <cuda_fp16.h>
#include <cub/cub.cuh>
#include <math.h>
#include <stdint.h>

// ---------------- constants ----------------
#define Hh 64
#define Ww 64
#define Cc 512
#define Mm 512
#define Nn 4
#define Aa 9
#define NPIX (Hh*Ww)              // 4096
#define NANCH (NPIX*Aa)           // 36864
#define PRE_N 3000
#define POST_N 300

#define LOC_OFF   0u
#define SCORE_OFF 589824u
#define ROIS_OFF  884736u
#define RI_OFF    889536u
#define ANCH_OFF  890736u

#define XSZ ((size_t)Nn*NPIX*Cc)   // elements per split term of x (NHWC)

// ---------------- static device scratch ----------------
__device__ float g_feat[(size_t)Nn*NPIX*Cc];            // NHWC feat fp32
__device__ __half g_xt[2*XSZ];                          // 2 fp16 split terms of x (term1 scaled 2^12)
__device__ __half g_ws[(size_t)2*9*512*512];            // 2 terms of W, [term][k][m][c]
__device__ float g_keys_in[Nn*NANCH];
__device__ float g_keys_out[Nn*NANCH];
__device__ int   g_vals_in[Nn*NANCH];
__device__ int   g_vals_out[Nn*NANCH];
__device__ int   g_offs[5];
__device__ float g_boxes[(size_t)Nn*NANCH*4];
__device__ float g_top[Nn*PRE_N*4];
__device__ float g_area[Nn*PRE_N];
__device__ unsigned long long g_cub_temp[(32u<<20)/8];  // 32MB

struct AB9 { float v[36]; };

// ================= helpers (baseline ISA only) =================
__device__ __forceinline__ uint32_t smem_u32(const void* p) {
    uint32_t a;
    asm("{ .reg .u64 t; cvta.to.shared.u64 t, %1; cvt.u32.u64 %0, t; }" : "=r"(a) : "l"(p));
    return a;
}
__device__ __forceinline__ void cp16(uint32_t dst, const void* src, int sz) {
    asm volatile("cp.async.ca.shared.global [%0], [%1], 16, %2;"
                 :: "r"(dst), "l"(__cvta_generic_to_global(src)), "r"(sz));
}
__device__ __forceinline__ void cp_commit() {
    asm volatile("cp.async.commit_group;" ::: "memory");
}
__device__ __forceinline__ void cp_wait2() {
    asm volatile("cp.async.wait_group 2;" ::: "memory");
}
__device__ __forceinline__ void cp_wait1() {
    asm volatile("cp.async.wait_group 1;" ::: "memory");
}
__device__ __forceinline__ void cp_wait0() {
    asm volatile("cp.async.wait_group 0;" ::: "memory");
}
__device__ __forceinline__ void ldsm4(uint32_t* r, uint32_t addr) {
    asm volatile("ldmatrix.sync.aligned.m8n8.x4.shared.b16 {%0,%1,%2,%3}, [%4];"
                 : "=r"(r[0]), "=r"(r[1]), "=r"(r[2]), "=r"(r[3]) : "r"(addr));
}
__device__ __forceinline__ void mma16816(float* d, const uint32_t* a, uint32_t b0, uint32_t b1) {
    asm volatile(
        "mma.sync.aligned.m16n8k16.row.col.f32.f16.f16.f32 "
        "{%0,%1,%2,%3}, {%4,%5,%6,%7}, {%8,%9}, {%0,%1,%2,%3};"
        : "+f"(d[0]), "+f"(d[1]), "+f"(d[2]), "+f"(d[3])
        : "r"(a[0]), "r"(a[1]), "r"(a[2]), "r"(a[3]), "r"(b0), "r"(b1));
}

// ================= setup: split x into 2 fp16 terms (term1 scaled 2^12), NCHW -> NHWC =====
__global__ void split_x_kernel(const float* __restrict__ x) {
    __shared__ float t[32][33];
    int n = blockIdx.z, c0 = blockIdx.x * 32, p0 = blockIdx.y * 32;
    int tx = threadIdx.x & 31, ty = threadIdx.x >> 5;
    const float* xn = x + (size_t)n * Cc * NPIX;
#pragma unroll
    for (int kk = 0; kk < 4; kk++) {
        int c = c0 + ty + kk * 8;
        t[ty + kk * 8][tx] = xn[(size_t)c * NPIX + p0 + tx];
    }
    __syncthreads();
#pragma unroll
    for (int kk = 0; kk < 4; kk++) {
        int p = p0 + ty + kk * 8;
        int c = c0 + tx;
        float v = t[tx][ty + kk * 8];
        __half a1 = __float2half_rn(v);
        float r1 = v - __half2float(a1);
        __half a2 = __float2half_rn(r1 * 4096.f);
        size_t idx = ((size_t)n * NPIX + p) * Cc + c;
        g_xt[idx] = a1;
        g_xt[XSZ + idx] = a2;
    }
}

// ================= setup: split W into 2 fp16 terms, OIHW -> [term][k][m][c] ========
__global__ void split_w_kernel(const float* __restrict__ w) {
    int idx = blockIdx.x * 256 + threadIdx.x;
    if (idx >= Mm * Cc) return;
    int m = idx >> 9, c = idx & 511;
#pragma unroll
    for (int k = 0; k < 9; k++) {
        float v = w[(size_t)m * (Cc * 9) + c * 9 + k];
        __half a1 = __float2half_rn(v);
        float r1 = v - __half2float(a1);
        __half a2 = __float2half_rn(r1 * 4096.f);
        size_t o = ((size_t)k * 512 + m) * 512 + c;
        g_ws[o] = a1;
        g_ws[(size_t)9 * 512 * 512 + o] = a2;
    }
}

// ================= HMMA implicit-GEMM conv (fp16x2 split, fp32 accum) =================
// grid (128 px-blocks of 128, 4 oc-blocks of 128), 256 threads (8 warps: 2m x 4n)
// 216 stages = 9 taps x 8 chunks(64ch) x 3 combos; 3-deep cp.async pipeline.
// Combos: 0 = a1*w1 -> acc0 ; 1 = a1*w2, 2 = a2*w1 -> accS (epilogue: acc0 + accS/4096)
#define NST 216
__device__ __constant__ int c_at[3] = {0, 0, 1};
__device__ __constant__ int c_wt[3] = {0, 1, 0};

__global__ __launch_bounds__(256, 1) void conv_hmma_kernel(const float* __restrict__ bias) {
    extern __shared__ char dsm_raw[];
    char* smem = dsm_raw + ((128 - ((uintptr_t)dsm_raw & 127)) & 127);
    // layout: 3 buffers of 32KB: [A 16KB | B 16KB]
    uint32_t base = smem_u32(smem);

    int tid = threadIdx.x;
    int wid = tid >> 5, lane = tid & 31;
    int wm = wid >> 2, wn = wid & 3;          // warp tile: m 64, n 32
    int pxb = blockIdx.x;                     // 128 px per block
    int oc0 = blockIdx.y * 128;

    float acc0[4][4][4];
    float accS[4][4][4];
#pragma unroll
    for (int i = 0; i < 4; i++)
#pragma unroll
        for (int j = 0; j < 4; j++)
#pragma unroll
            for (int k = 0; k < 4; k++) { acc0[i][j][k] = 0.f; accS[i][j][k] = 0.f; }

    for (int s = 0; s < NST + 2; s++) {
        // ---- issue loads for stage s into buffer s%3 ----
        if (s < NST) {
            int tap = s / 24;
            int rem = s % 24;
            int chunk = rem / 3;
            int combo = rem % 3;
            int dy = tap / 3 - 1, dx = tap % 3 - 1;
            uint32_t bufb = base + (uint32_t)(s % 3) * 32768u;
            const __half* xa = g_xt + (size_t)c_at[combo] * XSZ;
#pragma unroll
            for (int i = 0; i < 4; i++) {
                int v = tid + i * 256;         // 0..1023
                int r = v >> 3, c16 = v & 7;
                int P = pxb * 128 + r;
                int n = P >> 12, y = (P >> 6) & 63, x = P & 63;
                int yy = y + dy, xx = x + dx;
                bool ok = ((unsigned)yy < 64u) & ((unsigned)xx < 64u);
                int pix = (n << 12) + (ok ? ((yy << 6) + xx) : 0);
                const void* src = xa + ((size_t)pix << 9) + chunk * 64 + c16 * 8;
                uint32_t off = (uint32_t)(r * 128) + (uint32_t)((c16 * 16) ^ ((r & 7) << 4));
                cp16(bufb + off, src, ok ? 16 : 0);
            }
            const __half* wb = g_ws + (((size_t)c_wt[combo] * 9 + tap) * 512 + oc0) * 512;
#pragma unroll
            for (int i = 0; i < 4; i++) {
                int v = tid + i * 256;
                int r = v >> 3, c16 = v & 7;
                const void* src = wb + (size_t)r * 512 + chunk * 64 + c16 * 8;
                uint32_t off = (uint32_t)(r * 128) + (uint32_t)((c16 * 16) ^ ((r & 7) << 4));
                cp16(bufb + 16384u + off, src, 16);
            }
            cp_commit();
        }
        // ---- compute stage c = s-2 ----
        if (s >= 2) {
            int c = s - 2;
            if (s < NST) cp_wait2(); else if (s == NST) cp_wait1(); else cp_wait0();
            __syncthreads();
            int pcombo = c % 3;
            uint32_t aB = base + (uint32_t)(c % 3) * 32768u;
            uint32_t bB = aB + 16384u;
            int cg = lane >> 4;
            int arow0 = wm * 64 + (lane & 15);
            int brow0 = wn * 32 + (lane & 15);
#pragma unroll
            for (int ks = 0; ks < 4; ks++) {
                uint32_t coff = (uint32_t)((ks * 2 + cg) * 16);
                uint32_t a[4][4];
#pragma unroll
                for (int mt = 0; mt < 4; mt++) {
                    int row = arow0 + mt * 16;
                    uint32_t off = (uint32_t)(row * 128) + (coff ^ (uint32_t)((row & 7) << 4));
                    ldsm4(a[mt], aB + off);
                }
                uint32_t b[2][4];
#pragma unroll
                for (int bt = 0; bt < 2; bt++) {
                    int row = brow0 + bt * 16;
                    uint32_t off = (uint32_t)(row * 128) + (coff ^ (uint32_t)((row & 7) << 4));
                    ldsm4(b[bt], bB + off);
                }
                if (pcombo == 0) {
#pragma unroll
                    for (int mt = 0; mt < 4; mt++) {
                        mma16816(acc0[mt][0], a[mt], b[0][0], b[0][2]);
                        mma16816(acc0[mt][1], a[mt], b[0][1], b[0][3]);
                        mma16816(acc0[mt][2], a[mt], b[1][0], b[1][2]);
                        mma16816(acc0[mt][3], a[mt], b[1][1], b[1][3]);
                    }
                } else {
#pragma unroll
                    for (int mt = 0; mt < 4; mt++) {
                        mma16816(accS[mt][0], a[mt], b[0][0], b[0][2]);
                        mma16816(accS[mt][1], a[mt], b[0][1], b[0][3]);
                        mma16816(accS[mt][2], a[mt], b[1][0], b[1][2]);
                        mma16816(accS[mt][3], a[mt], b[1][1], b[1][3]);
                    }
                }
            }
            __syncthreads();   // protect buffer (c%3) reuse by loads at iter s+1
        }
    }

    // ---- epilogue: acc0 + accS/4096 + bias, relu -> g_feat (NHWC fp32) ----
    const float SC = 1.0f / 4096.0f;
#pragma unroll
    for (int mt = 0; mt < 4; mt++) {
        int px0 = pxb * 128 + wm * 64 + mt * 16 + (lane >> 2);
#pragma unroll
        for (int nt = 0; nt < 4; nt++) {
            int oc = oc0 + wn * 32 + nt * 8 + (lane & 3) * 2;
            float2 bv = *(const float2*)&bias[oc];
            float2 o0, o1;
            o0.x = fmaxf(fmaf(accS[mt][nt][0], SC, acc0[mt][nt][0]) + bv.x, 0.f);
            o0.y = fmaxf(fmaf(accS[mt][nt][1], SC, acc0[mt][nt][1]) + bv.y, 0.f);
            o1.x = fmaxf(fmaf(accS[mt][nt][2], SC, acc0[mt][nt][2]) + bv.x, 0.f);
            o1.y = fmaxf(fmaf(accS[mt][nt][3], SC, acc0[mt][nt][3]) + bv.y, 0.f);
            *(float2*)&g_feat[(size_t)px0 * 512 + oc] = o0;
            *(float2*)&g_feat[(size_t)(px0 + 8) * 512 + oc] = o1;
        }
    }
}

// ---------------- 1x1 head + softmax + decode + clip + mask ----------------
__device__ __forceinline__ float readdim(const void* p) {
    int v = *(const int*)p;
    if (v > 0 && v < 1048576) return (float)v;
    return *(const float*)p;
}

// grid (512, 4), 256 threads = 8 warps; warp handles one pixel
__global__ __launch_bounds__(256) void rpn_head_kernel(
    const float* __restrict__ w_score, const float* __restrict__ b_score,
    const float* __restrict__ w_loc,   const float* __restrict__ b_loc,
    AB9 ab, const void* ihp, const void* iwp, float* __restrict__ out) {
    __shared__ float sh[8][56];
    int wid = threadIdx.x >> 5, lane = threadIdx.x & 31;
    int p = blockIdx.x * 8 + wid;
    int n = blockIdx.y;

    const float* f = g_feat + ((size_t)n * NPIX + p) * Cc;
    float fv[16];
#pragma unroll
    for (int i = 0; i < 16; i++) fv[i] = f[lane + 32 * i];

#pragma unroll 1
    for (int o = 0; o < 18; o++) {
        const float* w = w_score + o * Cc;
        float a = 0.f;
#pragma unroll
        for (int i = 0; i < 16; i++) a = fmaf(fv[i], w[lane + 32 * i], a);
#pragma unroll
        for (int s = 16; s; s >>= 1) a += __shfl_xor_sync(0xffffffffu, a, s);
        if (lane == 0) sh[wid][o] = a + b_score[o];
    }
#pragma unroll 1
    for (int o = 0; o < 36; o++) {
        const float* w = w_loc + o * Cc;
        float a = 0.f;
#pragma unroll
        for (int i = 0; i < 16; i++) a = fmaf(fv[i], w[lane + 32 * i], a);
#pragma unroll
        for (int s = 16; s; s >>= 1) a += __shfl_xor_sync(0xffffffffu, a, s);
        if (lane == 0) sh[wid][18 + o] = a + b_loc[o];
    }
    __syncwarp();

    if (lane < 9) {
        int a = lane;
        float s0 = sh[wid][a * 2], s1 = sh[wid][a * 2 + 1];
        size_t pa = (size_t)n * NANCH + (size_t)p * 9 + a;
        out[SCORE_OFF + pa * 2 + 0] = s0;
        out[SCORE_OFF + pa * 2 + 1] = s1;
        float l0 = sh[wid][18 + a * 4 + 0];
        float l1 = sh[wid][18 + a * 4 + 1];
        float l2 = sh[wid][18 + a * 4 + 2];
        float l3 = sh[wid][18 + a * 4 + 3];
        out[LOC_OFF + pa * 4 + 0] = l0;
        out[LOC_OFF + pa * 4 + 1] = l1;
        out[LOC_OFF + pa * 4 + 2] = l2;
        out[LOC_OFF + pa * 4 + 3] = l3;

        int py = p >> 6, px = p & 63;
        float sx = px * 16.f, sy = py * 16.f;
        float a0 = sx + ab.v[a * 4 + 0];
        float a1 = sy + ab.v[a * 4 + 1];
        float a2 = sx + ab.v[a * 4 + 2];
        float a3 = sy + ab.v[a * 4 + 3];
        if (n == 0) {
            size_t q = ((size_t)p * 9 + a) * 4;
            out[ANCH_OFF + q + 0] = a0;
            out[ANCH_OFF + q + 1] = a1;
            out[ANCH_OFF + q + 2] = a2;
            out[ANCH_OFF + q + 3] = a3;
        }
        float aw = a2 - a0, ah = a3 - a1;
        float cx = a0 + 0.5f * aw, cy = a1 + 0.5f * ah;
        float ncx = l0 * aw + cx, ncy = l1 * ah + cy;
        float nw = expf(l2) * aw, nh = expf(l3) * ah;
        float r0 = ncx - 0.5f * nw, r1 = ncy - 0.5f * nh;
        float r2 = ncx + 0.5f * nw, r3 = ncy + 0.5f * nh;
        float Wd = readdim(iwp), Hd = readdim(ihp);
        r0 = fminf(fmaxf(r0, 0.f), Wd);
        r1 = fminf(fmaxf(r1, 0.f), Hd);
        r2 = fminf(fmaxf(r2, 0.f), Wd);
        r3 = fminf(fmaxf(r3, 0.f), Hd);
        bool valid = ((r2 - r0) >= 16.f) && ((r3 - r1) >= 16.f);
        float m = fmaxf(s0, s1);
        float e0 = expf(s0 - m), e1 = expf(s1 - m);
        float fg = __fdiv_rn(e1, e0 + e1);
        g_keys_in[pa] = valid ? fg : -1e9f;
        float4 b4; b4.x = r0; b4.y = r1; b4.z = r2; b4.w = r3;
        ((float4*)g_boxes)[pa] = b4;
    }
}

// ---------------- sort setup ----------------
__global__ void init_sort_kernel() {
    int idx = blockIdx.x * 256 + threadIdx.x;
    if (idx < Nn * NANCH) g_vals_in[idx] = idx % NANCH;
    if (idx < 5) g_offs[idx] = idx * NANCH;
}

// ---------------- gather top-3000 boxes ----------------
__global__ void gather_kernel() {
    int idx = blockIdx.x * 256 + threadIdx.x;
    if (idx >= Nn * PRE_N) return;
    int n = idx / PRE_N, i = idx % PRE_N;
    int v = g_vals_out[n * NANCH + i];
    float4 b = ((const float4*)g_boxes)[(size_t)n * NANCH + v];
    ((float4*)g_top)[idx] = b;
    g_area[idx] = (b.z - b.x) * (b.w - b.y);
}

// ---------------- greedy NMS, one block per image ----------------
__global__ __launch_bounds__(256) void nms_kernel(float* __restrict__ out) {
    int n = blockIdx.x;
    int tid = threadIdx.x;
    __shared__ unsigned char sup[PRE_N];
    __shared__ int sel[POST_N];
    for (int i = tid; i < PRE_N; i += 256) sup[i] = 0;
    __syncthreads();

    const float* B = g_top + n * PRE_N * 4;
    const float* A = g_area + n * PRE_N;
    int cnt = 0;
    for (int i = 0; i < PRE_N; i++) {
        if (sup[i]) continue;
        if (tid == 0) sel[cnt] = i;
        cnt++;
        if (cnt == POST_N) break;
        float x1 = B[i * 4 + 0], y1 = B[i * 4 + 1];
        float x2 = B[i * 4 + 2], y2 = B[i * 4 + 3];
        float ai = A[i];
        for (int j = i + 1 + tid; j < PRE_N; j += 256) {
            if (!sup[j]) {
                float xx1 = fmaxf(x1, B[j * 4 + 0]);
                float yy1 = fmaxf(y1, B[j * 4 + 1]);
                float xx2 = fminf(x2, B[j * 4 + 2]);
                float yy2 = fminf(y2, B[j * 4 + 3]);
                float inter = fmaxf(xx2 - xx1, 0.f) * fmaxf(yy2 - yy1, 0.f);
                float iou = __fdiv_rn(inter, ai + A[j] - inter + 1e-9f);
                if (iou > 0.7f) sup[j] = 1;
            }
        }
        __syncthreads();
    }
    __syncthreads();
    for (int k = tid; k < POST_N; k += 256) {
        int s = (k < cnt) ? sel[k] : 0;
        float4 b = ((const float4*)g_top)[n * PRE_N + s];
        size_t q = ((size_t)n * POST_N + k) * 4;
        out[ROIS_OFF + q + 0] = b.x;
        out[ROIS_OFF + q + 1] = b.y;
        out[ROIS_OFF + q + 2] = b.z;
        out[ROIS_OFF + q + 3] = b.w;
        out[RI_OFF + (size_t)n * POST_N + k] = (float)n;
    }
}

// ---------------- host: anchor base exactly like numpy (f64 -> f32) ----------------
static AB9 make_ab() {
    double ratios[3] = {0.5, 1.0, 2.0};
    double scales[3] = {8.0, 16.0, 32.0};
    AB9 r;
    for (int i = 0; i < 3; i++)
        for (int j = 0; j < 3; j++) {
            double h = 16.0 * scales[j] * sqrt(ratios[i]);
            double w = 16.0 * scales[j] * sqrt(1.0 / ratios[i]);
            int a = i * 3 + j;
            r.v[a * 4 + 0] = (float)(8.0 - w / 2.0);
            r.v[a * 4 + 1] = (float)(8.0 - h / 2.0);
            r.v[a * 4 + 2] = (float)(8.0 + w / 2.0);
            r.v[a * 4 + 3] = (float)(8.0 + h / 2.0);
        }
    return r;
}

extern "C" void kernel_launch(void* const* d_in, const int* in_sizes, int n_in,
                              void* d_out, int out_size) {
    const float* x       = (const float*)d_in[0];
    const float* w_conv  = (const float*)d_in[1];
    const float* b_conv  = (const float*)d_in[2];
    const float* w_score = (const float*)d_in[3];
    const float* b_score = (const float*)d_in[4];
    const float* w_loc   = (const float*)d_in[5];
    const float* b_loc   = (const float*)d_in[6];
    const void*  ihp     = d_in[7];
    const void*  iwp     = d_in[8];
    float* out = (float*)d_out;

    AB9 ab = make_ab();

    static int smem_set = 0;
    if (!smem_set) {
        cudaFuncSetAttribute(conv_hmma_kernel,
                             cudaFuncAttributeMaxDynamicSharedMemorySize, 98432);
        smem_set = 1;
    }

    // 1) split x -> 2 fp16 NHWC terms (term1 scaled 2^12); split W likewise
    split_x_kernel<<<dim3(Cc / 32, NPIX / 32, Nn), 256>>>(x);
    split_w_kernel<<<(Mm * Cc + 255) / 256, 256>>>(w_conv);

    // 2) HMMA implicit-GEMM 3x3 conv (fp16x2 split, 3 combos, dual-acc) + bias + relu
    conv_hmma_kernel<<<dim3(Nn * NPIX / 128, 4), 256, 98432>>>(b_conv);

    // 3) 1x1 heads + softmax + decode + clip + mask
    rpn_head_kernel<<<dim3(NPIX / 8, Nn), 256>>>(w_score, b_score, w_loc, b_loc,
                                                 ab, ihp, iwp, out);

    // 4) sort setup
    init_sort_kernel<<<(Nn * NANCH + 255) / 256, 256>>>();

    // 5) stable descending segmented sort (matches jax.lax.top_k tie semantics)
    void *keys_in, *keys_out, *vals_in, *vals_out, *offs, *tmp;
    cudaGetSymbolAddress(&keys_in, g_keys_in);
    cudaGetSymbolAddress(&keys_out, g_keys_out);
    cudaGetSymbolAddress(&vals_in, g_vals_in);
    cudaGetSymbolAddress(&vals_out, g_vals_out);
    cudaGetSymbolAddress(&offs, g_offs);
    cudaGetSymbolAddress(&tmp, g_cub_temp);
    size_t temp_bytes = sizeof(g_cub_temp);
    cub::DeviceSegmentedRadixSort::SortPairsDescending(
        tmp, temp_bytes,
        (const float*)keys_in, (float*)keys_out,
        (const int*)vals_in, (int*)vals_out,
        Nn * NANCH, Nn, (const int*)offs, (const int*)offs + 1,
        0, 32, (cudaStream_t)0);

    // 6) gather top-3000 boxes + areas
    gather_kernel<<<(Nn * PRE_N + 255) / 256, 256>>>();

    // 7) greedy NMS -> rois + roi_indices
    nms_kernel<<<Nn, 256>>>(out);
}

// round 11
// speedup vs baseline: 1.7519x; 1.0901x over previous
#include <cuda_runtime.h>
#include <cuda_fp16.h>
#include <cub/cub.cuh>
#include <math.h>
#include <stdint.h>

// ---------------- constants ----------------
#define Hh 64
#define Ww 64
#define Cc 512
#define Mm 512
#define Nn 4
#define Aa 9
#define NPIX (Hh*Ww)              // 4096
#define NANCH (NPIX*Aa)           // 36864
#define PRE_N 3000
#define POST_N 300

#define LOC_OFF   0u
#define SCORE_OFF 589824u
#define ROIS_OFF  884736u
#define RI_OFF    889536u
#define ANCH_OFF  890736u

#define XSZ ((size_t)Nn*NPIX*Cc)   // elements per split term of x (NHWC)
#define FSZ ((size_t)Nn*NPIX*Cc)   // feat elements

// ---------------- static device scratch ----------------
__device__ float g_feat0[FSZ];                          // main term a1*w1
__device__ float g_featS[FSZ];                          // small terms (x4096 scale)
__device__ __half g_xt[2*XSZ];                          // 2 fp16 split terms of x (term1 scaled 2^12)
__device__ __half g_ws[(size_t)2*9*512*512];            // 2 terms of W, [term][k][m][c]
__device__ float g_keys_in[Nn*NANCH];
__device__ float g_keys_out[Nn*NANCH];
__device__ int   g_vals_in[Nn*NANCH];
__device__ int   g_vals_out[Nn*NANCH];
__device__ int   g_offs[5];
__device__ float g_boxes[(size_t)Nn*NANCH*4];
__device__ float g_top[Nn*PRE_N*4];
__device__ float g_area[Nn*PRE_N];
__device__ unsigned long long g_cub_temp[(32u<<20)/8];  // 32MB

struct AB9 { float v[36]; };

// ================= helpers (baseline ISA only) =================
__device__ __forceinline__ uint32_t smem_u32(const void* p) {
    uint32_t a;
    asm("{ .reg .u64 t; cvta.to.shared.u64 t, %1; cvt.u32.u64 %0, t; }" : "=r"(a) : "l"(p));
    return a;
}
__device__ __forceinline__ void cp16(uint32_t dst, const void* src, int sz) {
    asm volatile("cp.async.ca.shared.global [%0], [%1], 16, %2;"
                 :: "r"(dst), "l"(__cvta_generic_to_global(src)), "r"(sz));
}
__device__ __forceinline__ void cp_commit() {
    asm volatile("cp.async.commit_group;" ::: "memory");
}
__device__ __forceinline__ void cp_wait2() {
    asm volatile("cp.async.wait_group 2;" ::: "memory");
}
__device__ __forceinline__ void cp_wait1() {
    asm volatile("cp.async.wait_group 1;" ::: "memory");
}
__device__ __forceinline__ void cp_wait0() {
    asm volatile("cp.async.wait_group 0;" ::: "memory");
}
__device__ __forceinline__ void ldsm4(uint32_t* r, uint32_t addr) {
    asm volatile("ldmatrix.sync.aligned.m8n8.x4.shared.b16 {%0,%1,%2,%3}, [%4];"
                 : "=r"(r[0]), "=r"(r[1]), "=r"(r[2]), "=r"(r[3]) : "r"(addr));
}
__device__ __forceinline__ void mma16816(float* d, const uint32_t* a, uint32_t b0, uint32_t b1) {
    asm volatile(
        "mma.sync.aligned.m16n8k16.row.col.f32.f16.f16.f32 "
        "{%0,%1,%2,%3}, {%4,%5,%6,%7}, {%8,%9}, {%0,%1,%2,%3};"
        : "+f"(d[0]), "+f"(d[1]), "+f"(d[2]), "+f"(d[3])
        : "r"(a[0]), "r"(a[1]), "r"(a[2]), "r"(a[3]), "r"(b0), "r"(b1));
}

// ================= setup: split x into 2 fp16 terms (term1 scaled 2^12), NCHW -> NHWC =====
__global__ void split_x_kernel(const float* __restrict__ x) {
    __shared__ float t[32][33];
    int n = blockIdx.z, c0 = blockIdx.x * 32, p0 = blockIdx.y * 32;
    int tx = threadIdx.x & 31, ty = threadIdx.x >> 5;
    const float* xn = x + (size_t)n * Cc * NPIX;
#pragma unroll
    for (int kk = 0; kk < 4; kk++) {
        int c = c0 + ty + kk * 8;
        t[ty + kk * 8][tx] = xn[(size_t)c * NPIX + p0 + tx];
    }
    __syncthreads();
#pragma unroll
    for (int kk = 0; kk < 4; kk++) {
        int p = p0 + ty + kk * 8;
        int c = c0 + tx;
        float v = t[tx][ty + kk * 8];
        __half a1 = __float2half_rn(v);
        float r1 = v - __half2float(a1);
        __half a2 = __float2half_rn(r1 * 4096.f);
        size_t idx = ((size_t)n * NPIX + p) * Cc + c;
        g_xt[idx] = a1;
        g_xt[XSZ + idx] = a2;
    }
}

// ================= setup: split W into 2 fp16 terms, OIHW -> [term][k][m][c] ========
__global__ void split_w_kernel(const float* __restrict__ w) {
    int idx = blockIdx.x * 256 + threadIdx.x;
    if (idx >= Mm * Cc) return;
    int m = idx >> 9, c = idx & 511;
#pragma unroll
    for (int k = 0; k < 9; k++) {
        float v = w[(size_t)m * (Cc * 9) + c * 9 + k];
        __half a1 = __float2half_rn(v);
        float r1 = v - __half2float(a1);
        __half a2 = __float2half_rn(r1 * 4096.f);
        size_t o = ((size_t)k * 512 + m) * 512 + c;
        g_ws[o] = a1;
        g_ws[(size_t)9 * 512 * 512 + o] = a2;
    }
}

// ================= zero the small-term feat accumulator =================
__global__ void zero_featS_kernel() {
    size_t i = (size_t)blockIdx.x * 256 + threadIdx.x;
    ((float4*)g_featS)[i] = make_float4(0.f, 0.f, 0.f, 0.f);
}

// ================= HMMA implicit-GEMM conv (fp16x2 split, fp32 accum) =================
// grid (128 px-blocks of 128, 4 oc-blocks of 128, 3 combos), 256 threads (8 warps: 2m x 4n)
// Each CTA: ONE combo, 72 stages = 9 taps x 8 chunks(64ch); 3-deep cp.async pipeline.
// Combo 0 = a1*w1 -> plain store to g_feat0 (exclusive tile)
// Combos 1,2 = a1*w2, a2*w1 (x4096 scale) -> atomicAdd to g_featS (exactly 2 adds/elem,
// fp32 add is commutative -> bit-deterministic)
#define NST 72
__device__ __constant__ int c_at[3] = {0, 0, 1};
__device__ __constant__ int c_wt[3] = {0, 1, 0};

__global__ __launch_bounds__(256, 2) void conv_hmma_kernel() {
    extern __shared__ char dsm_raw[];
    char* smem = dsm_raw + ((128 - ((uintptr_t)dsm_raw & 127)) & 127);
    // layout: 3 buffers of 32KB: [A 16KB | B 16KB]
    uint32_t base = smem_u32(smem);

    int tid = threadIdx.x;
    int wid = tid >> 5, lane = tid & 31;
    int wm = wid >> 2, wn = wid & 3;          // warp tile: m 64, n 32
    int pxb = blockIdx.x;                     // 128 px per block
    int oc0 = blockIdx.y * 128;
    int combo = blockIdx.z;

    const __half* xa = g_xt + (size_t)c_at[combo] * XSZ;
    const __half* wbase = g_ws + (size_t)c_wt[combo] * 9 * 512 * 512;

    float acc[4][4][4];
#pragma unroll
    for (int i = 0; i < 4; i++)
#pragma unroll
        for (int j = 0; j < 4; j++)
#pragma unroll
            for (int k = 0; k < 4; k++) acc[i][j][k] = 0.f;

    for (int s = 0; s < NST + 2; s++) {
        // ---- issue loads for stage s into buffer s%3 ----
        if (s < NST) {
            int tap = s >> 3;
            int chunk = s & 7;
            int dy = tap / 3 - 1, dx = tap % 3 - 1;
            uint32_t bufb = base + (uint32_t)(s % 3) * 32768u;
#pragma unroll
            for (int i = 0; i < 4; i++) {
                int v = tid + i * 256;         // 0..1023
                int r = v >> 3, c16 = v & 7;
                int P = pxb * 128 + r;
                int n = P >> 12, y = (P >> 6) & 63, x = P & 63;
                int yy = y + dy, xx = x + dx;
                bool ok = ((unsigned)yy < 64u) & ((unsigned)xx < 64u);
                int pix = (n << 12) + (ok ? ((yy << 6) + xx) : 0);
                const void* src = xa + ((size_t)pix << 9) + chunk * 64 + c16 * 8;
                uint32_t off = (uint32_t)(r * 128) + (uint32_t)((c16 * 16) ^ ((r & 7) << 4));
                cp16(bufb + off, src, ok ? 16 : 0);
            }
            const __half* wb = wbase + ((size_t)tap * 512 + oc0) * 512;
#pragma unroll
            for (int i = 0; i < 4; i++) {
                int v = tid + i * 256;
                int r = v >> 3, c16 = v & 7;
                const void* src = wb + (size_t)r * 512 + chunk * 64 + c16 * 8;
                uint32_t off = (uint32_t)(r * 128) + (uint32_t)((c16 * 16) ^ ((r & 7) << 4));
                cp16(bufb + 16384u + off, src, 16);
            }
            cp_commit();
        }
        // ---- compute stage c = s-2 ----
        if (s >= 2) {
            int c = s - 2;
            if (s < NST) cp_wait2(); else if (s == NST) cp_wait1(); else cp_wait0();
            __syncthreads();
            uint32_t aB = base + (uint32_t)(c % 3) * 32768u;
            uint32_t bB = aB + 16384u;
            int cg = lane >> 4;
            int arow0 = wm * 64 + (lane & 15);
            int brow0 = wn * 32 + (lane & 15);
#pragma unroll
            for (int ks = 0; ks < 4; ks++) {
                uint32_t coff = (uint32_t)((ks * 2 + cg) * 16);
                uint32_t a[4][4];
#pragma unroll
                for (int mt = 0; mt < 4; mt++) {
                    int row = arow0 + mt * 16;
                    uint32_t off = (uint32_t)(row * 128) + (coff ^ (uint32_t)((row & 7) << 4));
                    ldsm4(a[mt], aB + off);
                }
                uint32_t b[2][4];
#pragma unroll
                for (int bt = 0; bt < 2; bt++) {
                    int row = brow0 + bt * 16;
                    uint32_t off = (uint32_t)(row * 128) + (coff ^ (uint32_t)((row & 7) << 4));
                    ldsm4(b[bt], bB + off);
                }
#pragma unroll
                for (int mt = 0; mt < 4; mt++) {
                    mma16816(acc[mt][0], a[mt], b[0][0], b[0][2]);
                    mma16816(acc[mt][1], a[mt], b[0][1], b[0][3]);
                    mma16816(acc[mt][2], a[mt], b[1][0], b[1][2]);
                    mma16816(acc[mt][3], a[mt], b[1][1], b[1][3]);
                }
            }
            __syncthreads();   // protect buffer (c%3) reuse by loads at iter s+1
        }
    }

    // ---- epilogue ----
    if (combo == 0) {
#pragma unroll
        for (int mt = 0; mt < 4; mt++) {
            int px0 = pxb * 128 + wm * 64 + mt * 16 + (lane >> 2);
#pragma unroll
            for (int nt = 0; nt < 4; nt++) {
                int oc = oc0 + wn * 32 + nt * 8 + (lane & 3) * 2;
                float2 o0, o1;
                o0.x = acc[mt][nt][0]; o0.y = acc[mt][nt][1];
                o1.x = acc[mt][nt][2]; o1.y = acc[mt][nt][3];
                *(float2*)&g_feat0[(size_t)px0 * 512 + oc] = o0;
                *(float2*)&g_feat0[(size_t)(px0 + 8) * 512 + oc] = o1;
            }
        }
    } else {
#pragma unroll
        for (int mt = 0; mt < 4; mt++) {
            int px0 = pxb * 128 + wm * 64 + mt * 16 + (lane >> 2);
#pragma unroll
            for (int nt = 0; nt < 4; nt++) {
                int oc = oc0 + wn * 32 + nt * 8 + (lane & 3) * 2;
                atomicAdd(&g_featS[(size_t)px0 * 512 + oc],       acc[mt][nt][0]);
                atomicAdd(&g_featS[(size_t)px0 * 512 + oc + 1],   acc[mt][nt][1]);
                atomicAdd(&g_featS[(size_t)(px0 + 8) * 512 + oc],     acc[mt][nt][2]);
                atomicAdd(&g_featS[(size_t)(px0 + 8) * 512 + oc + 1], acc[mt][nt][3]);
            }
        }
    }
}

// ---------------- 1x1 head + merge/bias/relu + softmax + decode + clip + mask --------
__device__ __forceinline__ float readdim(const void* p) {
    int v = *(const int*)p;
    if (v > 0 && v < 1048576) return (float)v;
    return *(const float*)p;
}

// grid (512, 4), 256 threads = 8 warps; warp handles one pixel
__global__ __launch_bounds__(256) void rpn_head_kernel(
    const float* __restrict__ b_conv,
    const float* __restrict__ w_score, const float* __restrict__ b_score,
    const float* __restrict__ w_loc,   const float* __restrict__ b_loc,
    AB9 ab, const void* ihp, const void* iwp, float* __restrict__ out) {
    __shared__ float sh[8][56];
    int wid = threadIdx.x >> 5, lane = threadIdx.x & 31;
    int p = blockIdx.x * 8 + wid;
    int n = blockIdx.y;

    const float* f0 = g_feat0 + ((size_t)n * NPIX + p) * Cc;
    const float* fS = g_featS + ((size_t)n * NPIX + p) * Cc;
    const float SC = 1.0f / 4096.0f;
    float fv[16];
#pragma unroll
    for (int i = 0; i < 16; i++) {
        int c = lane + 32 * i;
        fv[i] = fmaxf(fmaf(fS[c], SC, f0[c]) + b_conv[c], 0.f);
    }

#pragma unroll 1
    for (int o = 0; o < 18; o++) {
        const float* w = w_score + o * Cc;
        float a = 0.f;
#pragma unroll
        for (int i = 0; i < 16; i++) a = fmaf(fv[i], w[lane + 32 * i], a);
#pragma unroll
        for (int s = 16; s; s >>= 1) a += __shfl_xor_sync(0xffffffffu, a, s);
        if (lane == 0) sh[wid][o] = a + b_score[o];
    }
#pragma unroll 1
    for (int o = 0; o < 36; o++) {
        const float* w = w_loc + o * Cc;
        float a = 0.f;
#pragma unroll
        for (int i = 0; i < 16; i++) a = fmaf(fv[i], w[lane + 32 * i], a);
#pragma unroll
        for (int s = 16; s; s >>= 1) a += __shfl_xor_sync(0xffffffffu, a, s);
        if (lane == 0) sh[wid][18 + o] = a + b_loc[o];
    }
    __syncwarp();

    if (lane < 9) {
        int a = lane;
        float s0 = sh[wid][a * 2], s1 = sh[wid][a * 2 + 1];
        size_t pa = (size_t)n * NANCH + (size_t)p * 9 + a;
        out[SCORE_OFF + pa * 2 + 0] = s0;
        out[SCORE_OFF + pa * 2 + 1] = s1;
        float l0 = sh[wid][18 + a * 4 + 0];
        float l1 = sh[wid][18 + a * 4 + 1];
        float l2 = sh[wid][18 + a * 4 + 2];
        float l3 = sh[wid][18 + a * 4 + 3];
        out[LOC_OFF + pa * 4 + 0] = l0;
        out[LOC_OFF + pa * 4 + 1] = l1;
        out[LOC_OFF + pa * 4 + 2] = l2;
        out[LOC_OFF + pa * 4 + 3] = l3;

        int py = p >> 6, px = p & 63;
        float sx = px * 16.f, sy = py * 16.f;
        float a0 = sx + ab.v[a * 4 + 0];
        float a1 = sy + ab.v[a * 4 + 1];
        float a2 = sx + ab.v[a * 4 + 2];
        float a3 = sy + ab.v[a * 4 + 3];
        if (n == 0) {
            size_t q = ((size_t)p * 9 + a) * 4;
            out[ANCH_OFF + q + 0] = a0;
            out[ANCH_OFF + q + 1] = a1;
            out[ANCH_OFF + q + 2] = a2;
            out[ANCH_OFF + q + 3] = a3;
        }
        float aw = a2 - a0, ah = a3 - a1;
        float cx = a0 + 0.5f * aw, cy = a1 + 0.5f * ah;
        float ncx = l0 * aw + cx, ncy = l1 * ah + cy;
        float nw = expf(l2) * aw, nh = expf(l3) * ah;
        float r0 = ncx - 0.5f * nw, r1 = ncy - 0.5f * nh;
        float r2 = ncx + 0.5f * nw, r3 = ncy + 0.5f * nh;
        float Wd = readdim(iwp), Hd = readdim(ihp);
        r0 = fminf(fmaxf(r0, 0.f), Wd);
        r1 = fminf(fmaxf(r1, 0.f), Hd);
        r2 = fminf(fmaxf(r2, 0.f), Wd);
        r3 = fminf(fmaxf(r3, 0.f), Hd);
        bool valid = ((r2 - r0) >= 16.f) && ((r3 - r1) >= 16.f);
        float m = fmaxf(s0, s1);
        float e0 = expf(s0 - m), e1 = expf(s1 - m);
        float fg = __fdiv_rn(e1, e0 + e1);
        g_keys_in[pa] = valid ? fg : -1e9f;
        float4 b4; b4.x = r0; b4.y = r1; b4.z = r2; b4.w = r3;
        ((float4*)g_boxes)[pa] = b4;
    }
}

// ---------------- sort setup ----------------
__global__ void init_sort_kernel() {
    int idx = blockIdx.x * 256 + threadIdx.x;
    if (idx < Nn * NANCH) g_vals_in[idx] = idx % NANCH;
    if (idx < 5) g_offs[idx] = idx * NANCH;
}

// ---------------- gather top-3000 boxes ----------------
__global__ void gather_kernel() {
    int idx = blockIdx.x * 256 + threadIdx.x;
    if (idx >= Nn * PRE_N) return;
    int n = idx / PRE_N, i = idx % PRE_N;
    int v = g_vals_out[n * NANCH + i];
    float4 b = ((const float4*)g_boxes)[(size_t)n * NANCH + v];
    ((float4*)g_top)[idx] = b;
    g_area[idx] = (b.z - b.x) * (b.w - b.y);
}

// ---------------- greedy NMS, one block per image ----------------
__global__ __launch_bounds__(256) void nms_kernel(float* __restrict__ out) {
    int n = blockIdx.x;
    int tid = threadIdx.x;
    __shared__ unsigned char sup[PRE_N];
    __shared__ int sel[POST_N];
    for (int i = tid; i < PRE_N; i += 256) sup[i] = 0;
    __syncthreads();

    const float* B = g_top + n * PRE_N * 4;
    const float* A = g_area + n * PRE_N;
    int cnt = 0;
    for (int i = 0; i < PRE_N; i++) {
        if (sup[i]) continue;
        if (tid == 0) sel[cnt] = i;
        cnt++;
        if (cnt == POST_N) break;
        float x1 = B[i * 4 + 0], y1 = B[i * 4 + 1];
        float x2 = B[i * 4 + 2], y2 = B[i * 4 + 3];
        float ai = A[i];
        for (int j = i + 1 + tid; j < PRE_N; j += 256) {
            if (!sup[j]) {
                float xx1 = fmaxf(x1, B[j * 4 + 0]);
                float yy1 = fmaxf(y1, B[j * 4 + 1]);
                float xx2 = fminf(x2, B[j * 4 + 2]);
                float yy2 = fminf(y2, B[j * 4 + 3]);
                float inter = fmaxf(xx2 - xx1, 0.f) * fmaxf(yy2 - yy1, 0.f);
                float iou = __fdiv_rn(inter, ai + A[j] - inter + 1e-9f);
                if (iou > 0.7f) sup[j] = 1;
            }
        }
        __syncthreads();
    }
    __syncthreads();
    for (int k = tid; k < POST_N; k += 256) {
        int s = (k < cnt) ? sel[k] : 0;
        float4 b = ((const float4*)g_top)[n * PRE_N + s];
        size_t q = ((size_t)n * POST_N + k) * 4;
        out[ROIS_OFF + q + 0] = b.x;
        out[ROIS_OFF + q + 1] = b.y;
        out[ROIS_OFF + q + 2] = b.z;
        out[ROIS_OFF + q + 3] = b.w;
        out[RI_OFF + (size_t)n * POST_N + k] = (float)n;
    }
}

// ---------------- host: anchor base exactly like numpy (f64 -> f32) ----------------
static AB9 make_ab() {
    double ratios[3] = {0.5, 1.0, 2.0};
    double scales[3] = {8.0, 16.0, 32.0};
    AB9 r;
    for (int i = 0; i < 3; i++)
        for (int j = 0; j < 3; j++) {
            double h = 16.0 * scales[j] * sqrt(ratios[i]);
            double w = 16.0 * scales[j] * sqrt(1.0 / ratios[i]);
            int a = i * 3 + j;
            r.v[a * 4 + 0] = (float)(8.0 - w / 2.0);
            r.v[a * 4 + 1] = (float)(8.0 - h / 2.0);
            r.v[a * 4 + 2] = (float)(8.0 + w / 2.0);
            r.v[a * 4 + 3] = (float)(8.0 + h / 2.0);
        }
    return r;
}

extern "C" void kernel_launch(void* const* d_in, const int* in_sizes, int n_in,
                              void* d_out, int out_size) {
    const float* x       = (const float*)d_in[0];
    const float* w_conv  = (const float*)d_in[1];
    const float* b_conv  = (const float*)d_in[2];
    const float* w_score = (const float*)d_in[3];
    const float* b_score = (const float*)d_in[4];
    const float* w_loc   = (const float*)d_in[5];
    const float* b_loc   = (const float*)d_in[6];
    const void*  ihp     = d_in[7];
    const void*  iwp     = d_in[8];
    float* out = (float*)d_out;

    AB9 ab = make_ab();

    static int smem_set = 0;
    if (!smem_set) {
        cudaFuncSetAttribute(conv_hmma_kernel,
                             cudaFuncAttributeMaxDynamicSharedMemorySize, 98432);
        smem_set = 1;
    }

    // 1) split x -> 2 fp16 NHWC terms (term1 scaled 2^12); split W likewise; zero featS
    split_x_kernel<<<dim3(Cc / 32, NPIX / 32, Nn), 256>>>(x);
    split_w_kernel<<<(Mm * Cc + 255) / 256, 256>>>(w_conv);
    zero_featS_kernel<<<FSZ / 4 / 256, 256>>>();

    // 2) HMMA implicit-GEMM 3x3 conv, combo-per-CTA (occupancy 2)
    conv_hmma_kernel<<<dim3(Nn * NPIX / 128, 4, 3), 256, 98432>>>();

    // 3) 1x1 heads (+merge/bias/relu) + softmax + decode + clip + mask
    rpn_head_kernel<<<dim3(NPIX / 8, Nn), 256>>>(b_conv, w_score, b_score, w_loc, b_loc,
                                                 ab, ihp, iwp, out);

    // 4) sort setup
    init_sort_kernel<<<(Nn * NANCH + 255) / 256, 256>>>();

    // 5) stable descending segmented sort (matches jax.lax.top_k tie semantics)
    void *keys_in, *keys_out, *vals_in, *vals_out, *offs, *tmp;
    cudaGetSymbolAddress(&keys_in, g_keys_in);
    cudaGetSymbolAddress(&keys_out, g_keys_out);
    cudaGetSymbolAddress(&vals_in, g_vals_in);
    cudaGetSymbolAddress(&vals_out, g_vals_out);
    cudaGetSymbolAddress(&offs, g_offs);
    cudaGetSymbolAddress(&tmp, g_cub_temp);
    size_t temp_bytes = sizeof(g_cub_temp);
    cub::DeviceSegmentedRadixSort::SortPairsDescending(
        tmp, temp_bytes,
        (const float*)keys_in, (float*)keys_out,
        (const int*)vals_in, (int*)vals_out,
        Nn * NANCH, Nn, (const int*)offs, (const int*)offs + 1,
        0, 32, (cudaStream_t)0);

    // 6) gather top-3000 boxes + areas
    gather_kernel<<<(Nn * PRE_N + 255) / 256, 256>>>();

    // 7) greedy NMS -> rois + roi_indices
    nms_kernel<<<Nn, 256>>>(out);
}

// round 13
// speedup vs baseline: 1.8827x; 1.0746x over previous
#include <cuda_runtime.h>
#include <cuda_fp16.h>
#include <cub/cub.cuh>
#include <math.h>
#include <stdint.h>

// ---------------- constants ----------------
#define Hh 64
#define Ww 64
#define Cc 512
#define Mm 512
#define Nn 4
#define Aa 9
#define NPIX (Hh*Ww)              // 4096
#define NANCH (NPIX*Aa)           // 36864
#define PRE_N 3000
#define POST_N 300

#define LOC_OFF   0u
#define SCORE_OFF 589824u
#define ROIS_OFF  884736u
#define RI_OFF    889536u
#define ANCH_OFF  890736u

#define XSZ ((size_t)Nn*NPIX*Cc)   // elements per split term of x (NHWC)
#define FSZ ((size_t)Nn*NPIX*Cc)   // feat elements

// ---------------- static device scratch ----------------
__device__ float g_feat0[FSZ];                          // main term a1*w1
__device__ float g_featS[FSZ];                          // small terms (x4096 scale)
__device__ __half g_xt[2*XSZ];                          // 2 fp16 split terms of x (term1 scaled 2^12)
__device__ __half g_ws[(size_t)2*9*512*512];            // 2 terms of W, [term][k][m][c]
__device__ unsigned long long g_k64_in[Nn*NANCH];       // composed sort keys
__device__ unsigned long long g_k64_out[Nn*NANCH];
__device__ int   g_vals_in[Nn*NANCH];
__device__ int   g_vals_out[Nn*NANCH];
__device__ float g_boxes[(size_t)Nn*NANCH*4];
__device__ float g_top[Nn*PRE_N*4];
__device__ float g_area[Nn*PRE_N];
__device__ unsigned long long g_cub_temp[(32u<<20)/8];  // 32MB

struct AB9 { float v[36]; };

// ================= helpers (baseline ISA only) =================
__device__ __forceinline__ uint32_t smem_u32(const void* p) {
    uint32_t a;
    asm("{ .reg .u64 t; cvta.to.shared.u64 t, %1; cvt.u32.u64 %0, t; }" : "=r"(a) : "l"(p));
    return a;
}
__device__ __forceinline__ void cp16(uint32_t dst, const void* src, int sz) {
    asm volatile("cp.async.ca.shared.global [%0], [%1], 16, %2;"
                 :: "r"(dst), "l"(__cvta_generic_to_global(src)), "r"(sz));
}
__device__ __forceinline__ void cp_commit() {
    asm volatile("cp.async.commit_group;" ::: "memory");
}
__device__ __forceinline__ void cp_wait2() {
    asm volatile("cp.async.wait_group 2;" ::: "memory");
}
__device__ __forceinline__ void cp_wait1() {
    asm volatile("cp.async.wait_group 1;" ::: "memory");
}
__device__ __forceinline__ void cp_wait0() {
    asm volatile("cp.async.wait_group 0;" ::: "memory");
}
__device__ __forceinline__ void ldsm4(uint32_t* r, uint32_t addr) {
    asm volatile("ldmatrix.sync.aligned.m8n8.x4.shared.b16 {%0,%1,%2,%3}, [%4];"
                 : "=r"(r[0]), "=r"(r[1]), "=r"(r[2]), "=r"(r[3]) : "r"(addr));
}
__device__ __forceinline__ void mma16816(float* d, const uint32_t* a, uint32_t b0, uint32_t b1) {
    asm volatile(
        "mma.sync.aligned.m16n8k16.row.col.f32.f16.f16.f32 "
        "{%0,%1,%2,%3}, {%4,%5,%6,%7}, {%8,%9}, {%0,%1,%2,%3};"
        : "+f"(d[0]), "+f"(d[1]), "+f"(d[2]), "+f"(d[3])
        : "r"(a[0]), "r"(a[1]), "r"(a[2]), "r"(a[3]), "r"(b0), "r"(b1));
}

// ================= setup: split x into 2 fp16 terms (term1 scaled 2^12), NCHW -> NHWC =====
__global__ void split_x_kernel(const float* __restrict__ x) {
    __shared__ float t[32][33];
    int n = blockIdx.z, c0 = blockIdx.x * 32, p0 = blockIdx.y * 32;
    int tx = threadIdx.x & 31, ty = threadIdx.x >> 5;
    const float* xn = x + (size_t)n * Cc * NPIX;
#pragma unroll
    for (int kk = 0; kk < 4; kk++) {
        int c = c0 + ty + kk * 8;
        t[ty + kk * 8][tx] = xn[(size_t)c * NPIX + p0 + tx];
    }
    __syncthreads();
#pragma unroll
    for (int kk = 0; kk < 4; kk++) {
        int p = p0 + ty + kk * 8;
        int c = c0 + tx;
        float v = t[tx][ty + kk * 8];
        __half a1 = __float2half_rn(v);
        float r1 = v - __half2float(a1);
        __half a2 = __float2half_rn(r1 * 4096.f);
        size_t idx = ((size_t)n * NPIX + p) * Cc + c;
        g_xt[idx] = a1;
        g_xt[XSZ + idx] = a2;
    }
}

// ================= setup: split W into 2 fp16 terms, OIHW -> [term][k][m][c] ========
__global__ void split_w_kernel(const float* __restrict__ w) {
    int idx = blockIdx.x * 256 + threadIdx.x;
    if (idx >= Mm * Cc) return;
    int m = idx >> 9, c = idx & 511;
#pragma unroll
    for (int k = 0; k < 9; k++) {
        float v = w[(size_t)m * (Cc * 9) + c * 9 + k];
        __half a1 = __float2half_rn(v);
        float r1 = v - __half2float(a1);
        __half a2 = __float2half_rn(r1 * 4096.f);
        size_t o = ((size_t)k * 512 + m) * 512 + c;
        g_ws[o] = a1;
        g_ws[(size_t)9 * 512 * 512 + o] = a2;
    }
}

// ================= zero the small-term feat accumulator =================
__global__ void zero_featS_kernel() {
    size_t i = (size_t)blockIdx.x * 256 + threadIdx.x;
    ((float4*)g_featS)[i] = make_float4(0.f, 0.f, 0.f, 0.f);
}

// ================= HMMA implicit-GEMM conv (fp16x2 split, fp32 accum) =================
// grid (128 px-blocks of 128, 4 oc-blocks of 128, 3 combos), 256 threads (8 warps: 2m x 4n)
// Each CTA: ONE combo, 72 stages = 9 taps x 8 chunks(64ch); 3-deep cp.async pipeline.
#define NST 72
__device__ __constant__ int c_at[3] = {0, 0, 1};
__device__ __constant__ int c_wt[3] = {0, 1, 0};

__global__ __launch_bounds__(256, 2) void conv_hmma_kernel() {
    extern __shared__ char dsm_raw[];
    char* smem = dsm_raw + ((128 - ((uintptr_t)dsm_raw & 127)) & 127);
    uint32_t base = smem_u32(smem);

    int tid = threadIdx.x;
    int wid = tid >> 5, lane = tid & 31;
    int wm = wid >> 2, wn = wid & 3;          // warp tile: m 64, n 32
    int pxb = blockIdx.x;                     // 128 px per block
    int oc0 = blockIdx.y * 128;
    int combo = blockIdx.z;

    const __half* xa = g_xt + (size_t)c_at[combo] * XSZ;
    const __half* wbase = g_ws + (size_t)c_wt[combo] * 9 * 512 * 512;

    float acc[4][4][4];
#pragma unroll
    for (int i = 0; i < 4; i++)
#pragma unroll
        for (int j = 0; j < 4; j++)
#pragma unroll
            for (int k = 0; k < 4; k++) acc[i][j][k] = 0.f;

    for (int s = 0; s < NST + 2; s++) {
        if (s < NST) {
            int tap = s >> 3;
            int chunk = s & 7;
            int dy = tap / 3 - 1, dx = tap % 3 - 1;
            uint32_t bufb = base + (uint32_t)(s % 3) * 32768u;
#pragma unroll
            for (int i = 0; i < 4; i++) {
                int v = tid + i * 256;
                int r = v >> 3, c16 = v & 7;
                int P = pxb * 128 + r;
                int n = P >> 12, y = (P >> 6) & 63, x = P & 63;
                int yy = y + dy, xx = x + dx;
                bool ok = ((unsigned)yy < 64u) & ((unsigned)xx < 64u);
                int pix = (n << 12) + (ok ? ((yy << 6) + xx) : 0);
                const void* src = xa + ((size_t)pix << 9) + chunk * 64 + c16 * 8;
                uint32_t off = (uint32_t)(r * 128) + (uint32_t)((c16 * 16) ^ ((r & 7) << 4));
                cp16(bufb + off, src, ok ? 16 : 0);
            }
            const __half* wb = wbase + ((size_t)tap * 512 + oc0) * 512;
#pragma unroll
            for (int i = 0; i < 4; i++) {
                int v = tid + i * 256;
                int r = v >> 3, c16 = v & 7;
                const void* src = wb + (size_t)r * 512 + chunk * 64 + c16 * 8;
                uint32_t off = (uint32_t)(r * 128) + (uint32_t)((c16 * 16) ^ ((r & 7) << 4));
                cp16(bufb + 16384u + off, src, 16);
            }
            cp_commit();
        }
        if (s >= 2) {
            int c = s - 2;
            if (s < NST) cp_wait2(); else if (s == NST) cp_wait1(); else cp_wait0();
            __syncthreads();
            uint32_t aB = base + (uint32_t)(c % 3) * 32768u;
            uint32_t bB = aB + 16384u;
            int cg = lane >> 4;
            int arow0 = wm * 64 + (lane & 15);
            int brow0 = wn * 32 + (lane & 15);
#pragma unroll
            for (int ks = 0; ks < 4; ks++) {
                uint32_t coff = (uint32_t)((ks * 2 + cg) * 16);
                uint32_t a[4][4];
#pragma unroll
                for (int mt = 0; mt < 4; mt++) {
                    int row = arow0 + mt * 16;
                    uint32_t off = (uint32_t)(row * 128) + (coff ^ (uint32_t)((row & 7) << 4));
                    ldsm4(a[mt], aB + off);
                }
                uint32_t b[2][4];
#pragma unroll
                for (int bt = 0; bt < 2; bt++) {
                    int row = brow0 + bt * 16;
                    uint32_t off = (uint32_t)(row * 128) + (coff ^ (uint32_t)((row & 7) << 4));
                    ldsm4(b[bt], bB + off);
                }
#pragma unroll
                for (int mt = 0; mt < 4; mt++) {
                    mma16816(acc[mt][0], a[mt], b[0][0], b[0][2]);
                    mma16816(acc[mt][1], a[mt], b[0][1], b[0][3]);
                    mma16816(acc[mt][2], a[mt], b[1][0], b[1][2]);
                    mma16816(acc[mt][3], a[mt], b[1][1], b[1][3]);
                }
            }
            __syncthreads();
        }
    }

    // ---- epilogue ----
    if (combo == 0) {
#pragma unroll
        for (int mt = 0; mt < 4; mt++) {
            int px0 = pxb * 128 + wm * 64 + mt * 16 + (lane >> 2);
#pragma unroll
            for (int nt = 0; nt < 4; nt++) {
                int oc = oc0 + wn * 32 + nt * 8 + (lane & 3) * 2;
                float2 o0, o1;
                o0.x = acc[mt][nt][0]; o0.y = acc[mt][nt][1];
                o1.x = acc[mt][nt][2]; o1.y = acc[mt][nt][3];
                *(float2*)&g_feat0[(size_t)px0 * 512 + oc] = o0;
                *(float2*)&g_feat0[(size_t)(px0 + 8) * 512 + oc] = o1;
            }
        }
    } else {
#pragma unroll
        for (int mt = 0; mt < 4; mt++) {
            int px0 = pxb * 128 + wm * 64 + mt * 16 + (lane >> 2);
#pragma unroll
            for (int nt = 0; nt < 4; nt++) {
                int oc = oc0 + wn * 32 + nt * 8 + (lane & 3) * 2;
                atomicAdd(&g_featS[(size_t)px0 * 512 + oc],       acc[mt][nt][0]);
                atomicAdd(&g_featS[(size_t)px0 * 512 + oc + 1],   acc[mt][nt][1]);
                atomicAdd(&g_featS[(size_t)(px0 + 8) * 512 + oc],     acc[mt][nt][2]);
                atomicAdd(&g_featS[(size_t)(px0 + 8) * 512 + oc + 1], acc[mt][nt][3]);
            }
        }
    }
}

// ---------------- 1x1 head + merge/bias/relu + softmax + decode + clip + mask --------
__device__ __forceinline__ float readdim(const void* p) {
    int v = *(const int*)p;
    if (v > 0 && v < 1048576) return (float)v;
    return *(const float*)p;
}

// grid (512, 4), 256 threads = 8 warps; warp handles one pixel
__global__ __launch_bounds__(256) void rpn_head_kernel(
    const float* __restrict__ b_conv,
    const float* __restrict__ w_score, const float* __restrict__ b_score,
    const float* __restrict__ w_loc,   const float* __restrict__ b_loc,
    AB9 ab, const void* ihp, const void* iwp, float* __restrict__ out) {
    __shared__ float sh[8][56];
    int wid = threadIdx.x >> 5, lane = threadIdx.x & 31;
    int p = blockIdx.x * 8 + wid;
    int n = blockIdx.y;

    const float* f0 = g_feat0 + ((size_t)n * NPIX + p) * Cc;
    const float* fS = g_featS + ((size_t)n * NPIX + p) * Cc;
    const float SC = 1.0f / 4096.0f;
    float fv[16];
#pragma unroll
    for (int i = 0; i < 16; i++) {
        int c = lane + 32 * i;
        fv[i] = fmaxf(fmaf(fS[c], SC, f0[c]) + b_conv[c], 0.f);
    }

#pragma unroll 1
    for (int o = 0; o < 18; o++) {
        const float* w = w_score + o * Cc;
        float a = 0.f;
#pragma unroll
        for (int i = 0; i < 16; i++) a = fmaf(fv[i], w[lane + 32 * i], a);
#pragma unroll
        for (int s = 16; s; s >>= 1) a += __shfl_xor_sync(0xffffffffu, a, s);
        if (lane == 0) sh[wid][o] = a + b_score[o];
    }
#pragma unroll 1
    for (int o = 0; o < 36; o++) {
        const float* w = w_loc + o * Cc;
        float a = 0.f;
#pragma unroll
        for (int i = 0; i < 16; i++) a = fmaf(fv[i], w[lane + 32 * i], a);
#pragma unroll
        for (int s = 16; s; s >>= 1) a += __shfl_xor_sync(0xffffffffu, a, s);
        if (lane == 0) sh[wid][18 + o] = a + b_loc[o];
    }
    __syncwarp();

    if (lane < 9) {
        int a = lane;
        float s0 = sh[wid][a * 2], s1 = sh[wid][a * 2 + 1];
        size_t pa = (size_t)n * NANCH + (size_t)p * 9 + a;
        out[SCORE_OFF + pa * 2 + 0] = s0;
        out[SCORE_OFF + pa * 2 + 1] = s1;
        float l0 = sh[wid][18 + a * 4 + 0];
        float l1 = sh[wid][18 + a * 4 + 1];
        float l2 = sh[wid][18 + a * 4 + 2];
        float l3 = sh[wid][18 + a * 4 + 3];
        out[LOC_OFF + pa * 4 + 0] = l0;
        out[LOC_OFF + pa * 4 + 1] = l1;
        out[LOC_OFF + pa * 4 + 2] = l2;
        out[LOC_OFF + pa * 4 + 3] = l3;

        int py = p >> 6, px = p & 63;
        float sx = px * 16.f, sy = py * 16.f;
        float a0 = sx + ab.v[a * 4 + 0];
        float a1 = sy + ab.v[a * 4 + 1];
        float a2 = sx + ab.v[a * 4 + 2];
        float a3 = sy + ab.v[a * 4 + 3];
        if (n == 0) {
            size_t q = ((size_t)p * 9 + a) * 4;
            out[ANCH_OFF + q + 0] = a0;
            out[ANCH_OFF + q + 1] = a1;
            out[ANCH_OFF + q + 2] = a2;
            out[ANCH_OFF + q + 3] = a3;
        }
        float aw = a2 - a0, ah = a3 - a1;
        float cx = a0 + 0.5f * aw, cy = a1 + 0.5f * ah;
        float ncx = l0 * aw + cx, ncy = l1 * ah + cy;
        float nw = expf(l2) * aw, nh = expf(l3) * ah;
        float r0 = ncx - 0.5f * nw, r1 = ncy - 0.5f * nh;
        float r2 = ncx + 0.5f * nw, r3 = ncy + 0.5f * nh;
        float Wd = readdim(iwp), Hd = readdim(ihp);
        r0 = fminf(fmaxf(r0, 0.f), Wd);
        r1 = fminf(fmaxf(r1, 0.f), Hd);
        r2 = fminf(fmaxf(r2, 0.f), Wd);
        r3 = fminf(fmaxf(r3, 0.f), Hd);
        bool valid = ((r2 - r0) >= 16.f) && ((r3 - r1) >= 16.f);
        float m = fmaxf(s0, s1);
        float e0 = expf(s0 - m), e1 = expf(s1 - m);
        float fg = __fdiv_rn(e1, e0 + e1);
        float key = valid ? fg : -1e9f;
        // composed 64-bit sort key: [33:32]=image, [31:0]=~ordered(score)
        // ascending stable sort => per-image descending score, ties by index (== lax.top_k)
        uint32_t bits = __float_as_uint(key);
        uint32_t u_asc = bits ^ ((bits & 0x80000000u) ? 0xFFFFFFFFu : 0x80000000u);
        g_k64_in[pa] = ((unsigned long long)n << 32) | (unsigned long long)(~u_asc);
        float4 b4; b4.x = r0; b4.y = r1; b4.z = r2; b4.w = r3;
        ((float4*)g_boxes)[pa] = b4;
    }
}

// ---------------- sort setup ----------------
__global__ void init_sort_kernel() {
    int idx = blockIdx.x * 256 + threadIdx.x;
    if (idx < Nn * NANCH) g_vals_in[idx] = idx;   // global anchor index
}

// ---------------- gather top-3000 boxes ----------------
__global__ void gather_kernel() {
    int idx = blockIdx.x * 256 + threadIdx.x;
    if (idx >= Nn * PRE_N) return;
    int n = idx / PRE_N, i = idx % PRE_N;
    int v = g_vals_out[n * NANCH + i];            // global anchor index (sorted)
    float4 b = ((const float4*)g_boxes)[v];
    ((float4*)g_top)[idx] = b;
    g_area[idx] = (b.z - b.x) * (b.w - b.y);
}

// ---------------- greedy NMS, one block per image ----------------
__global__ __launch_bounds__(256) void nms_kernel(float* __restrict__ out) {
    int n = blockIdx.x;
    int tid = threadIdx.x;
    __shared__ unsigned char sup[PRE_N];
    __shared__ int sel[POST_N];
    for (int i = tid; i < PRE_N; i += 256) sup[i] = 0;
    __syncthreads();

    const float* B = g_top + n * PRE_N * 4;
    const float* A = g_area + n * PRE_N;
    int cnt = 0;
    for (int i = 0; i < PRE_N; i++) {
        if (sup[i]) continue;
        if (tid == 0) sel[cnt] = i;
        cnt++;
        if (cnt == POST_N) break;
        float x1 = B[i * 4 + 0], y1 = B[i * 4 + 1];
        float x2 = B[i * 4 + 2], y2 = B[i * 4 + 3];
        float ai = A[i];
        for (int j = i + 1 + tid; j < PRE_N; j += 256) {
            if (!sup[j]) {
                float xx1 = fmaxf(x1, B[j * 4 + 0]);
                float yy1 = fmaxf(y1, B[j * 4 + 1]);
                float xx2 = fminf(x2, B[j * 4 + 2]);
                float yy2 = fminf(y2, B[j * 4 + 3]);
                float inter = fmaxf(xx2 - xx1, 0.f) * fmaxf(yy2 - yy1, 0.f);
                float iou = __fdiv_rn(inter, ai + A[j] - inter + 1e-9f);
                if (iou > 0.7f) sup[j] = 1;
            }
        }
        __syncthreads();
    }
    __syncthreads();
    for (int k = tid; k < POST_N; k += 256) {
        int s = (k < cnt) ? sel[k] : 0;
        float4 b = ((const float4*)g_top)[n * PRE_N + s];
        size_t q = ((size_t)n * POST_N + k) * 4;
        out[ROIS_OFF + q + 0] = b.x;
        out[ROIS_OFF + q + 1] = b.y;
        out[ROIS_OFF + q + 2] = b.z;
        out[ROIS_OFF + q + 3] = b.w;
        out[RI_OFF + (size_t)n * POST_N + k] = (float)n;
    }
}

// ---------------- host: anchor base exactly like numpy (f64 -> f32) ----------------
static AB9 make_ab() {
    double ratios[3] = {0.5, 1.0, 2.0};
    double scales[3] = {8.0, 16.0, 32.0};
    AB9 r;
    for (int i = 0; i < 3; i++)
        for (int j = 0; j < 3; j++) {
            double h = 16.0 * scales[j] * sqrt(ratios[i]);
            double w = 16.0 * scales[j] * sqrt(1.0 / ratios[i]);
            int a = i * 3 + j;
            r.v[a * 4 + 0] = (float)(8.0 - w / 2.0);
            r.v[a * 4 + 1] = (float)(8.0 - h / 2.0);
            r.v[a * 4 + 2] = (float)(8.0 + w / 2.0);
            r.v[a * 4 + 3] = (float)(8.0 + h / 2.0);
        }
    return r;
}

extern "C" void kernel_launch(void* const* d_in, const int* in_sizes, int n_in,
                              void* d_out, int out_size) {
    const float* x       = (const float*)d_in[0];
    const float* w_conv  = (const float*)d_in[1];
    const float* b_conv  = (const float*)d_in[2];
    const float* w_score = (const float*)d_in[3];
    const float* b_score = (const float*)d_in[4];
    const float* w_loc   = (const float*)d_in[5];
    const float* b_loc   = (const float*)d_in[6];
    const void*  ihp     = d_in[7];
    const void*  iwp     = d_in[8];
    float* out = (float*)d_out;

    AB9 ab = make_ab();

    static int smem_set = 0;
    if (!smem_set) {
        cudaFuncSetAttribute(conv_hmma_kernel,
                             cudaFuncAttributeMaxDynamicSharedMemorySize, 98432);
        smem_set = 1;
    }

    // 1) split x -> 2 fp16 NHWC terms (term1 scaled 2^12); split W likewise; zero featS
    split_x_kernel<<<dim3(Cc / 32, NPIX / 32, Nn), 256>>>(x);
    split_w_kernel<<<(Mm * Cc + 255) / 256, 256>>>(w_conv);
    zero_featS_kernel<<<FSZ / 4 / 256, 256>>>();

    // 2) HMMA implicit-GEMM 3x3 conv, combo-per-CTA (occupancy 2)
    conv_hmma_kernel<<<dim3(Nn * NPIX / 128, 4, 3), 256, 98432>>>();

    // 3) 1x1 heads (+merge/bias/relu) + softmax + decode + clip + mask + key compose
    rpn_head_kernel<<<dim3(NPIX / 8, Nn), 256>>>(b_conv, w_score, b_score, w_loc, b_loc,
                                                 ab, ihp, iwp, out);

    // 4) sort setup
    init_sort_kernel<<<(Nn * NANCH + 255) / 256, 256>>>();

    // 5) ONE full-device stable radix sort over composed 64-bit keys (bits [0,34))
    void *k64_in, *k64_out, *vals_in, *vals_out, *tmp;
    cudaGetSymbolAddress(&k64_in, g_k64_in);
    cudaGetSymbolAddress(&k64_out, g_k64_out);
    cudaGetSymbolAddress(&vals_in, g_vals_in);
    cudaGetSymbolAddress(&vals_out, g_vals_out);
    cudaGetSymbolAddress(&tmp, g_cub_temp);
    size_t temp_bytes = sizeof(g_cub_temp);
    cub::DeviceRadixSort::SortPairs(
        tmp, temp_bytes,
        (const unsigned long long*)k64_in, (unsigned long long*)k64_out,
        (const int*)vals_in, (int*)vals_out,
        Nn * NANCH, 0, 34, (cudaStream_t)0);

    // 6) gather top-3000 boxes + areas
    gather_kernel<<<(Nn * PRE_N + 255) / 256, 256>>>();

    // 7) greedy NMS -> rois + roi_indices
    nms_kernel<<<Nn, 256>>>(out);
}

// round 17
// speedup vs baseline: 2.9217x; 1.5519x over previous
#include <cuda_runtime.h>
#include <cuda_fp16.h>
#include <cub/cub.cuh>
#include <math.h>
#include <stdint.h>

// ---------------- constants ----------------
#define Hh 64
#define Ww 64
#define Cc 512
#define Mm 512
#define Nn 4
#define Aa 9
#define NPIX (Hh*Ww)              // 4096
#define NANCH (NPIX*Aa)           // 36864
#define PRE_N 3000
#define POST_N 300
#define NW 47                     // 64-bit words per NMS mask row (3000/64 -> 47)

#define LOC_OFF   0u
#define SCORE_OFF 589824u
#define ROIS_OFF  884736u
#define RI_OFF    889536u
#define ANCH_OFF  890736u

#define XSZ ((size_t)Nn*NPIX*Cc)   // elements per split term of x (NHWC)
#define FSZ ((size_t)Nn*NPIX*Cc)   // feat elements

// ---------------- static device scratch ----------------
__device__ float g_feat0[FSZ];                          // main term a1*w1
__device__ float g_featS[FSZ];                          // small terms (x4096 scale)
__device__ __half g_xt[2*XSZ];                          // 2 fp16 split terms of x (term1 scaled 2^12)
__device__ __half g_ws[(size_t)2*9*512*512];            // 2 terms of W, [term][k][m][c]
__device__ unsigned long long g_k64_in[Nn*NANCH];       // composed sort keys
__device__ unsigned long long g_k64_out[Nn*NANCH];
__device__ int   g_vals_in[Nn*NANCH];
__device__ int   g_vals_out[Nn*NANCH];
__device__ float g_boxes[(size_t)Nn*NANCH*4];
__device__ float g_top[Nn*PRE_N*4];
__device__ float g_area[Nn*PRE_N];
__device__ unsigned long long g_nmsmask[(size_t)Nn*PRE_N*NW];   // 4.5MB IoU bitmask
__device__ unsigned long long g_cub_temp[(32u<<20)/8];  // 32MB

struct AB9 { float v[36]; };

// ================= helpers (baseline ISA only) =================
__device__ __forceinline__ uint32_t smem_u32(const void* p) {
    uint32_t a;
    asm("{ .reg .u64 t; cvta.to.shared.u64 t, %1; cvt.u32.u64 %0, t; }" : "=r"(a) : "l"(p));
    return a;
}
__device__ __forceinline__ void cp16(uint32_t dst, const void* src, int sz) {
    asm volatile("cp.async.ca.shared.global [%0], [%1], 16, %2;"
                 :: "r"(dst), "l"(__cvta_generic_to_global(src)), "r"(sz));
}
__device__ __forceinline__ void cp_commit() {
    asm volatile("cp.async.commit_group;" ::: "memory");
}
__device__ __forceinline__ void cp_wait2() {
    asm volatile("cp.async.wait_group 2;" ::: "memory");
}
__device__ __forceinline__ void cp_wait1() {
    asm volatile("cp.async.wait_group 1;" ::: "memory");
}
__device__ __forceinline__ void cp_wait0() {
    asm volatile("cp.async.wait_group 0;" ::: "memory");
}
__device__ __forceinline__ void ldsm4(uint32_t* r, uint32_t addr) {
    asm volatile("ldmatrix.sync.aligned.m8n8.x4.shared.b16 {%0,%1,%2,%3}, [%4];"
                 : "=r"(r[0]), "=r"(r[1]), "=r"(r[2]), "=r"(r[3]) : "r"(addr));
}
__device__ __forceinline__ void mma16816(float* d, const uint32_t* a, uint32_t b0, uint32_t b1) {
    asm volatile(
        "mma.sync.aligned.m16n8k16.row.col.f32.f16.f16.f32 "
        "{%0,%1,%2,%3}, {%4,%5,%6,%7}, {%8,%9}, {%0,%1,%2,%3};"
        : "+f"(d[0]), "+f"(d[1]), "+f"(d[2]), "+f"(d[3])
        : "r"(a[0]), "r"(a[1]), "r"(a[2]), "r"(a[3]), "r"(b0), "r"(b1));
}

// ================= setup: split x into 2 fp16 terms (term1 scaled 2^12), NCHW -> NHWC =====
__global__ void split_x_kernel(const float* __restrict__ x) {
    __shared__ float t[32][33];
    int n = blockIdx.z, c0 = blockIdx.x * 32, p0 = blockIdx.y * 32;
    int tx = threadIdx.x & 31, ty = threadIdx.x >> 5;
    const float* xn = x + (size_t)n * Cc * NPIX;
#pragma unroll
    for (int kk = 0; kk < 4; kk++) {
        int c = c0 + ty + kk * 8;
        t[ty + kk * 8][tx] = xn[(size_t)c * NPIX + p0 + tx];
    }
    __syncthreads();
#pragma unroll
    for (int kk = 0; kk < 4; kk++) {
        int p = p0 + ty + kk * 8;
        int c = c0 + tx;
        float v = t[tx][ty + kk * 8];
        __half a1 = __float2half_rn(v);
        float r1 = v - __half2float(a1);
        __half a2 = __float2half_rn(r1 * 4096.f);
        size_t idx = ((size_t)n * NPIX + p) * Cc + c;
        g_xt[idx] = a1;
        g_xt[XSZ + idx] = a2;
    }
}

// ================= setup: split W into 2 fp16 terms, OIHW -> [term][k][m][c] ========
__global__ void split_w_kernel(const float* __restrict__ w) {
    int idx = blockIdx.x * 256 + threadIdx.x;
    if (idx >= Mm * Cc) return;
    int m = idx >> 9, c = idx & 511;
#pragma unroll
    for (int k = 0; k < 9; k++) {
        float v = w[(size_t)m * (Cc * 9) + c * 9 + k];
        __half a1 = __float2half_rn(v);
        float r1 = v - __half2float(a1);
        __half a2 = __float2half_rn(r1 * 4096.f);
        size_t o = ((size_t)k * 512 + m) * 512 + c;
        g_ws[o] = a1;
        g_ws[(size_t)9 * 512 * 512 + o] = a2;
    }
}

// ================= zero the small-term feat accumulator =================
__global__ void zero_featS_kernel() {
    size_t i = (size_t)blockIdx.x * 256 + threadIdx.x;
    ((float4*)g_featS)[i] = make_float4(0.f, 0.f, 0.f, 0.f);
}

// ================= HMMA implicit-GEMM conv (fp16x2 split, fp32 accum) =================
// grid (128 px-blocks of 128, 4 oc-blocks of 128, 3 combos), 256 threads (8 warps: 2m x 4n)
#define NST 72
__device__ __constant__ int c_at[3] = {0, 0, 1};
__device__ __constant__ int c_wt[3] = {0, 1, 0};

__global__ __launch_bounds__(256, 2) void conv_hmma_kernel() {
    extern __shared__ char dsm_raw[];
    char* smem = dsm_raw + ((128 - ((uintptr_t)dsm_raw & 127)) & 127);
    uint32_t base = smem_u32(smem);

    int tid = threadIdx.x;
    int wid = tid >> 5, lane = tid & 31;
    int wm = wid >> 2, wn = wid & 3;          // warp tile: m 64, n 32
    int pxb = blockIdx.x;                     // 128 px per block
    int oc0 = blockIdx.y * 128;
    int combo = blockIdx.z;

    const __half* xa = g_xt + (size_t)c_at[combo] * XSZ;
    const __half* wbase = g_ws + (size_t)c_wt[combo] * 9 * 512 * 512;

    float acc[4][4][4];
#pragma unroll
    for (int i = 0; i < 4; i++)
#pragma unroll
        for (int j = 0; j < 4; j++)
#pragma unroll
            for (int k = 0; k < 4; k++) acc[i][j][k] = 0.f;

    for (int s = 0; s < NST + 2; s++) {
        if (s < NST) {
            int tap = s >> 3;
            int chunk = s & 7;
            int dy = tap / 3 - 1, dx = tap % 3 - 1;
            uint32_t bufb = base + (uint32_t)(s % 3) * 32768u;
#pragma unroll
            for (int i = 0; i < 4; i++) {
                int v = tid + i * 256;
                int r = v >> 3, c16 = v & 7;
                int P = pxb * 128 + r;
                int n = P >> 12, y = (P >> 6) & 63, x = P & 63;
                int yy = y + dy, xx = x + dx;
                bool ok = ((unsigned)yy < 64u) & ((unsigned)xx < 64u);
                int pix = (n << 12) + (ok ? ((yy << 6) + xx) : 0);
                const void* src = xa + ((size_t)pix << 9) + chunk * 64 + c16 * 8;
                uint32_t off = (uint32_t)(r * 128) + (uint32_t)((c16 * 16) ^ ((r & 7) << 4));
                cp16(bufb + off, src, ok ? 16 : 0);
            }
            const __half* wb = wbase + ((size_t)tap * 512 + oc0) * 512;
#pragma unroll
            for (int i = 0; i < 4; i++) {
                int v = tid + i * 256;
                int r = v >> 3, c16 = v & 7;
                const void* src = wb + (size_t)r * 512 + chunk * 64 + c16 * 8;
                uint32_t off = (uint32_t)(r * 128) + (uint32_t)((c16 * 16) ^ ((r & 7) << 4));
                cp16(bufb + 16384u + off, src, 16);
            }
            cp_commit();
        }
        if (s >= 2) {
            int c = s - 2;
            if (s < NST) cp_wait2(); else if (s == NST) cp_wait1(); else cp_wait0();
            __syncthreads();
            uint32_t aB = base + (uint32_t)(c % 3) * 32768u;
            uint32_t bB = aB + 16384u;
            int cg = lane >> 4;
            int arow0 = wm * 64 + (lane & 15);
            int brow0 = wn * 32 + (lane & 15);
#pragma unroll
            for (int ks = 0; ks < 4; ks++) {
                uint32_t coff = (uint32_t)((ks * 2 + cg) * 16);
                uint32_t a[4][4];
#pragma unroll
                for (int mt = 0; mt < 4; mt++) {
                    int row = arow0 + mt * 16;
                    uint32_t off = (uint32_t)(row * 128) + (coff ^ (uint32_t)((row & 7) << 4));
                    ldsm4(a[mt], aB + off);
                }
                uint32_t b[2][4];
#pragma unroll
                for (int bt = 0; bt < 2; bt++) {
                    int row = brow0 + bt * 16;
                    uint32_t off = (uint32_t)(row * 128) + (coff ^ (uint32_t)((row & 7) << 4));
                    ldsm4(b[bt], bB + off);
                }
#pragma unroll
                for (int mt = 0; mt < 4; mt++) {
                    mma16816(acc[mt][0], a[mt], b[0][0], b[0][2]);
                    mma16816(acc[mt][1], a[mt], b[0][1], b[0][3]);
                    mma16816(acc[mt][2], a[mt], b[1][0], b[1][2]);
                    mma16816(acc[mt][3], a[mt], b[1][1], b[1][3]);
                }
            }
            __syncthreads();
        }
    }

    // ---- epilogue ----
    if (combo == 0) {
#pragma unroll
        for (int mt = 0; mt < 4; mt++) {
            int px0 = pxb * 128 + wm * 64 + mt * 16 + (lane >> 2);
#pragma unroll
            for (int nt = 0; nt < 4; nt++) {
                int oc = oc0 + wn * 32 + nt * 8 + (lane & 3) * 2;
                float2 o0, o1;
                o0.x = acc[mt][nt][0]; o0.y = acc[mt][nt][1];
                o1.x = acc[mt][nt][2]; o1.y = acc[mt][nt][3];
                *(float2*)&g_feat0[(size_t)px0 * 512 + oc] = o0;
                *(float2*)&g_feat0[(size_t)(px0 + 8) * 512 + oc] = o1;
            }
        }
    } else {
#pragma unroll
        for (int mt = 0; mt < 4; mt++) {
            int px0 = pxb * 128 + wm * 64 + mt * 16 + (lane >> 2);
#pragma unroll
            for (int nt = 0; nt < 4; nt++) {
                int oc = oc0 + wn * 32 + nt * 8 + (lane & 3) * 2;
                atomicAdd(&g_featS[(size_t)px0 * 512 + oc],       acc[mt][nt][0]);
                atomicAdd(&g_featS[(size_t)px0 * 512 + oc + 1],   acc[mt][nt][1]);
                atomicAdd(&g_featS[(size_t)(px0 + 8) * 512 + oc],     acc[mt][nt][2]);
                atomicAdd(&g_featS[(size_t)(px0 + 8) * 512 + oc + 1], acc[mt][nt][3]);
            }
        }
    }
}

// ---------------- 1x1 head + merge/bias/relu + softmax + decode + clip + mask --------
__device__ __forceinline__ float readdim(const void* p) {
    int v = *(const int*)p;
    if (v > 0 && v < 1048576) return (float)v;
    return *(const float*)p;
}

// grid (512, 4), 256 threads = 8 warps; warp handles one pixel
__global__ __launch_bounds__(256) void rpn_head_kernel(
    const float* __restrict__ b_conv,
    const float* __restrict__ w_score, const float* __restrict__ b_score,
    const float* __restrict__ w_loc,   const float* __restrict__ b_loc,
    AB9 ab, const void* ihp, const void* iwp, float* __restrict__ out) {
    __shared__ float sh[8][56];
    int wid = threadIdx.x >> 5, lane = threadIdx.x & 31;
    int p = blockIdx.x * 8 + wid;
    int n = blockIdx.y;

    const float* f0 = g_feat0 + ((size_t)n * NPIX + p) * Cc;
    const float* fS = g_featS + ((size_t)n * NPIX + p) * Cc;
    const float SC = 1.0f / 4096.0f;
    float fv[16];
#pragma unroll
    for (int i = 0; i < 16; i++) {
        int c = lane + 32 * i;
        fv[i] = fmaxf(fmaf(fS[c], SC, f0[c]) + b_conv[c], 0.f);
    }

#pragma unroll 1
    for (int o = 0; o < 18; o++) {
        const float* w = w_score + o * Cc;
        float a = 0.f;
#pragma unroll
        for (int i = 0; i < 16; i++) a = fmaf(fv[i], w[lane + 32 * i], a);
#pragma unroll
        for (int s = 16; s; s >>= 1) a += __shfl_xor_sync(0xffffffffu, a, s);
        if (lane == 0) sh[wid][o] = a + b_score[o];
    }
#pragma unroll 1
    for (int o = 0; o < 36; o++) {
        const float* w = w_loc + o * Cc;
        float a = 0.f;
#pragma unroll
        for (int i = 0; i < 16; i++) a = fmaf(fv[i], w[lane + 32 * i], a);
#pragma unroll
        for (int s = 16; s; s >>= 1) a += __shfl_xor_sync(0xffffffffu, a, s);
        if (lane == 0) sh[wid][18 + o] = a + b_loc[o];
    }
    __syncwarp();

    if (lane < 9) {
        int a = lane;
        float s0 = sh[wid][a * 2], s1 = sh[wid][a * 2 + 1];
        size_t pa = (size_t)n * NANCH + (size_t)p * 9 + a;
        out[SCORE_OFF + pa * 2 + 0] = s0;
        out[SCORE_OFF + pa * 2 + 1] = s1;
        float l0 = sh[wid][18 + a * 4 + 0];
        float l1 = sh[wid][18 + a * 4 + 1];
        float l2 = sh[wid][18 + a * 4 + 2];
        float l3 = sh[wid][18 + a * 4 + 3];
        out[LOC_OFF + pa * 4 + 0] = l0;
        out[LOC_OFF + pa * 4 + 1] = l1;
        out[LOC_OFF + pa * 4 + 2] = l2;
        out[LOC_OFF + pa * 4 + 3] = l3;

        int py = p >> 6, px = p & 63;
        float sx = px * 16.f, sy = py * 16.f;
        float a0 = sx + ab.v[a * 4 + 0];
        float a1 = sy + ab.v[a * 4 + 1];
        float a2 = sx + ab.v[a * 4 + 2];
        float a3 = sy + ab.v[a * 4 + 3];
        if (n == 0) {
            size_t q = ((size_t)p * 9 + a) * 4;
            out[ANCH_OFF + q + 0] = a0;
            out[ANCH_OFF + q + 1] = a1;
            out[ANCH_OFF + q + 2] = a2;
            out[ANCH_OFF + q + 3] = a3;
        }
        float aw = a2 - a0, ah = a3 - a1;
        float cx = a0 + 0.5f * aw, cy = a1 + 0.5f * ah;
        float ncx = l0 * aw + cx, ncy = l1 * ah + cy;
        float nw = expf(l2) * aw, nh = expf(l3) * ah;
        float r0 = ncx - 0.5f * nw, r1 = ncy - 0.5f * nh;
        float r2 = ncx + 0.5f * nw, r3 = ncy + 0.5f * nh;
        float Wd = readdim(iwp), Hd = readdim(ihp);
        r0 = fminf(fmaxf(r0, 0.f), Wd);
        r1 = fminf(fmaxf(r1, 0.f), Hd);
        r2 = fminf(fmaxf(r2, 0.f), Wd);
        r3 = fminf(fmaxf(r3, 0.f), Hd);
        bool valid = ((r2 - r0) >= 16.f) && ((r3 - r1) >= 16.f);
        float m = fmaxf(s0, s1);
        float e0 = expf(s0 - m), e1 = expf(s1 - m);
        float fg = __fdiv_rn(e1, e0 + e1);
        float key = valid ? fg : -1e9f;
        // composed 64-bit sort key: [33:32]=image, [31:0]=~ordered(score)
        uint32_t bits = __float_as_uint(key);
        uint32_t u_asc = bits ^ ((bits & 0x80000000u) ? 0xFFFFFFFFu : 0x80000000u);
        g_k64_in[pa] = ((unsigned long long)n << 32) | (unsigned long long)(~u_asc);
        g_vals_in[pa] = (int)pa;
        float4 b4; b4.x = r0; b4.y = r1; b4.z = r2; b4.w = r3;
        ((float4*)g_boxes)[pa] = b4;
    }
}

// ---------------- gather top-3000 boxes ----------------
__global__ void gather_kernel() {
    int idx = blockIdx.x * 256 + threadIdx.x;
    if (idx >= Nn * PRE_N) return;
    int n = idx / PRE_N, i = idx % PRE_N;
    int v = g_vals_out[n * NANCH + i];            // global anchor index (sorted)
    float4 b = ((const float4*)g_boxes)[v];
    ((float4*)g_top)[idx] = b;
    g_area[idx] = (b.z - b.x) * (b.w - b.y);
}

// ---------------- NMS phase 1: full-parallel IoU bitmask (3000x3000 per image) ------
__global__ void nms_mask_kernel() {
    int idx = blockIdx.x * 256 + threadIdx.x;
    if (idx >= Nn * PRE_N * NW) return;
    int w = idx % NW;
    int i = (idx / NW) % PRE_N;
    int n = idx / (NW * PRE_N);
    float4 bi = ((const float4*)g_top)[n * PRE_N + i];
    float ai = g_area[n * PRE_N + i];
    unsigned long long m = 0ull;
    int j0 = w * 64;
    int jend = PRE_N - j0; if (jend > 64) jend = 64;
    for (int b = 0; b < jend; b++) {
        int j = j0 + b;
        float4 bj = ((const float4*)g_top)[n * PRE_N + j];
        float aj = g_area[n * PRE_N + j];
        float xx1 = fmaxf(bi.x, bj.x), yy1 = fmaxf(bi.y, bj.y);
        float xx2 = fminf(bi.z, bj.z), yy2 = fminf(bi.w, bj.w);
        float inter = fmaxf(xx2 - xx1, 0.f) * fmaxf(yy2 - yy1, 0.f);
        float iou = __fdiv_rn(inter, ai + aj - inter + 1e-9f);
        if (iou > 0.7f) m |= (1ull << b);
    }
    g_nmsmask[idx] = m;
}

// ---------------- NMS phase 2: one warp per image, serial greedy reduce -------------
__global__ __launch_bounds__(64) void nms_reduce_kernel(float* __restrict__ out) {
    int n = blockIdx.x, tid = threadIdx.x, lane = tid & 31;
    __shared__ unsigned long long removed[NW];
    __shared__ int sel[POST_N];
    __shared__ int scnt;
    if (tid < NW) removed[tid] = 0ull;
    if (tid == 0) scnt = 0;
    __syncthreads();

    if (tid < 32) {
        int cnt = 0;
        const unsigned long long VLAST = (1ull << (PRE_N - (NW - 1) * 64)) - 1ull;
        for (int wi = 0; wi < NW && cnt < POST_N; wi++) {
            unsigned long long vmask = (wi == NW - 1) ? VLAST : ~0ull;
            for (;;) {
                unsigned long long live = (~removed[wi]) & vmask;
                if (!live || cnt >= POST_N) break;
                int b = __ffsll((long long)live) - 1;
                int i = wi * 64 + b;
                if (lane == 0) sel[cnt] = i;
                cnt++;
                const unsigned long long* row = g_nmsmask + ((size_t)n * PRE_N + i) * NW;
                if (lane < NW) removed[lane] |= row[lane];
                int l2 = lane + 32;
                if (l2 < NW) removed[l2] |= row[l2];
                __syncwarp();
                // diagonal bit of row i guarantees removed[i] is now set,
                // so recomputing live from removed is exact.
            }
        }
        if (lane == 0) scnt = cnt;
    }
    __syncthreads();

    int cnt = scnt;
    for (int k = tid; k < POST_N; k += 64) {
        int s = (k < cnt) ? sel[k] : 0;   // pad with top box (index 0, always kept)
        float4 b = ((const float4*)g_top)[n * PRE_N + s];
        size_t q = ((size_t)n * POST_N + k) * 4;
        out[ROIS_OFF + q + 0] = b.x;
        out[ROIS_OFF + q + 1] = b.y;
        out[ROIS_OFF + q + 2] = b.z;
        out[ROIS_OFF + q + 3] = b.w;
        out[RI_OFF + (size_t)n * POST_N + k] = (float)n;
    }
}

// ---------------- host: anchor base exactly like numpy (f64 -> f32) ----------------
static AB9 make_ab() {
    double ratios[3] = {0.5, 1.0, 2.0};
    double scales[3] = {8.0, 16.0, 32.0};
    AB9 r;
    for (int i = 0; i < 3; i++)
        for (int j = 0; j < 3; j++) {
            double h = 16.0 * scales[j] * sqrt(ratios[i]);
            double w = 16.0 * scales[j] * sqrt(1.0 / ratios[i]);
            int a = i * 3 + j;
            r.v[a * 4 + 0] = (float)(8.0 - w / 2.0);
            r.v[a * 4 + 1] = (float)(8.0 - h / 2.0);
            r.v[a * 4 + 2] = (float)(8.0 + w / 2.0);
            r.v[a * 4 + 3] = (float)(8.0 + h / 2.0);
        }
    return r;
}

extern "C" void kernel_launch(void* const* d_in, const int* in_sizes, int n_in,
                              void* d_out, int out_size) {
    const float* x       = (const float*)d_in[0];
    const float* w_conv  = (const float*)d_in[1];
    const float* b_conv  = (const float*)d_in[2];
    const float* w_score = (const float*)d_in[3];
    const float* b_score = (const float*)d_in[4];
    const float* w_loc   = (const float*)d_in[5];
    const float* b_loc   = (const float*)d_in[6];
    const void*  ihp     = d_in[7];
    const void*  iwp     = d_in[8];
    float* out = (float*)d_out;

    AB9 ab = make_ab();

    static int smem_set = 0;
    if (!smem_set) {
        cudaFuncSetAttribute(conv_hmma_kernel,
                             cudaFuncAttributeMaxDynamicSharedMemorySize, 98432);
        smem_set = 1;
    }

    // 1) split x -> 2 fp16 NHWC terms (term1 scaled 2^12); split W likewise; zero featS
    split_x_kernel<<<dim3(Cc / 32, NPIX / 32, Nn), 256>>>(x);
    split_w_kernel<<<(Mm * Cc + 255) / 256, 256>>>(w_conv);
    zero_featS_kernel<<<FSZ / 4 / 256, 256>>>();

    // 2) HMMA implicit-GEMM 3x3 conv, combo-per-CTA (occupancy 2)
    conv_hmma_kernel<<<dim3(Nn * NPIX / 128, 4, 3), 256, 98432>>>();

    // 3) 1x1 heads (+merge/bias/relu) + softmax + decode + clip + keys + vals
    rpn_head_kernel<<<dim3(NPIX / 8, Nn), 256>>>(b_conv, w_score, b_score, w_loc, b_loc,
                                                 ab, ihp, iwp, out);

    // 4) ONE full-device stable radix sort over composed 64-bit keys (bits [0,34))
    void *k64_in, *k64_out, *vals_in, *vals_out, *tmp;
    cudaGetSymbolAddress(&k64_in, g_k64_in);
    cudaGetSymbolAddress(&k64_out, g_k64_out);
    cudaGetSymbolAddress(&vals_in, g_vals_in);
    cudaGetSymbolAddress(&vals_out, g_vals_out);
    cudaGetSymbolAddress(&tmp, g_cub_temp);
    size_t temp_bytes = sizeof(g_cub_temp);
    cub::DeviceRadixSort::SortPairs(
        tmp, temp_bytes,
        (const unsigned long long*)k64_in, (unsigned long long*)k64_out,
        (const int*)vals_in, (int*)vals_out,
        Nn * NANCH, 0, 34, (cudaStream_t)0);

    // 5) gather top-3000 boxes + areas
    gather_kernel<<<(Nn * PRE_N + 255) / 256, 256>>>();

    // 6) NMS: parallel bitmask + warp-serial greedy reduce -> rois + roi_indices
    nms_mask_kernel<<<(Nn * PRE_N * NW + 255) / 256, 256>>>();
    nms_reduce_kernel<<<Nn, 64>>>(out);
}